// round 5
// baseline (speedup 1.0000x reference)
#include <cuda_runtime.h>
#include <math.h>

#define B_ 32
#define C_ 512
#define L_ 32
#define P_ 8
#define D_ 64
#define N_ 1024   // L*L

// ---------------- scratch (alloc-free rule: __device__ globals) ----------------
__device__ float g_q[(size_t)B_ * P_ * N_ * D_];   // 64 MB
__device__ float g_k[(size_t)B_ * P_ * N_ * D_];   // 64 MB (k + rp folded in)
__device__ float g_v[(size_t)B_ * P_ * N_ * D_];   // 64 MB
__device__ float g_rp[(size_t)P_ * N_ * D_];       // 2 MB

// ---------------- kernel 0: relative position table ----------------
// rp[p][n][d] = h_pos[h,0,c] + w_pos[0,w,c], n=h*32+w, c=p*64+d
__global__ void rp_kernel(const float* __restrict__ h_pos,
                          const float* __restrict__ w_pos) {
    int idx = blockIdx.x * blockDim.x + threadIdx.x;   // < P_*N_*D_ = 524288
    if (idx >= P_ * N_ * D_) return;
    int dd = idx & 63;
    int n  = (idx >> 6) & (N_ - 1);
    int p  = idx >> 16;
    int h  = n >> 5, w = n & 31;
    int c  = p * 64 + dd;
    g_rp[idx] = h_pos[h * C_ + c] + w_pos[w * C_ + c];
}

// ---------------- kernel 1: QKV GEMM (Out[n,o] = sum_c X[b,c,n] * W[o,c]) ----------------
// Tile 128(n) x 128(o), BK=16, 256 threads, 8x8 per-thread microtile.
// Epilogue scatters into [b,p,n,d] head layout; k-tiles add rp.
__global__ __launch_bounds__(256)
void qkv_kernel(const float* __restrict__ x, const float* __restrict__ w) {
    __shared__ float As[16][128];   // [c][n]
    __shared__ float Bs[16][128];   // [c][o]

    const int b  = blockIdx.z;
    const int o0 = blockIdx.x * 128;   // 0..1535
    const int n0 = blockIdx.y * 128;   // 0..1023
    const int tid = threadIdx.x;
    const int tx = tid & 15, ty = tid >> 4;

    const float* xb = x + (size_t)b * C_ * N_;

    float acc[8][8];
#pragma unroll
    for (int i = 0; i < 8; i++)
#pragma unroll
        for (int j = 0; j < 8; j++) acc[i][j] = 0.f;

    for (int k0 = 0; k0 < C_; k0 += 16) {
        // load X tile -> As[c][n]  (coalesced float4 along n)
#pragma unroll
        for (int pp = 0; pp < 2; pp++) {
            int kk = (tid >> 5) + pp * 8;
            int n4 = tid & 31;
            float4 v = *(const float4*)&xb[(size_t)(k0 + kk) * N_ + n0 + n4 * 4];
            *(float4*)&As[kk][n4 * 4] = v;
        }
        // load W tile -> Bs[c][o]  (float4 along c, transposed scalar store)
#pragma unroll
        for (int pp = 0; pp < 2; pp++) {
            int row = (tid >> 2) + pp * 64;
            int c4  = tid & 3;
            float4 v = *(const float4*)&w[(size_t)(o0 + row) * C_ + k0 + c4 * 4];
            Bs[c4 * 4 + 0][row] = v.x;
            Bs[c4 * 4 + 1][row] = v.y;
            Bs[c4 * 4 + 2][row] = v.z;
            Bs[c4 * 4 + 3][row] = v.w;
        }
        __syncthreads();
#pragma unroll
        for (int kk = 0; kk < 16; kk++) {
            float a[8], bb[8];
            *(float4*)&a[0]  = *(float4*)&As[kk][ty * 8];
            *(float4*)&a[4]  = *(float4*)&As[kk][ty * 8 + 4];
            *(float4*)&bb[0] = *(float4*)&Bs[kk][tx * 8];
            *(float4*)&bb[4] = *(float4*)&Bs[kk][tx * 8 + 4];
#pragma unroll
            for (int i = 0; i < 8; i++)
#pragma unroll
                for (int j = 0; j < 8; j++)
                    acc[i][j] += a[i] * bb[j];
        }
        __syncthreads();
    }

    // epilogue: whole block lies in one of q/k/v (o-tile of 128 within 512-chunk)
    const int which = o0 >> 9;                 // 0=q 1=k 2=v
    const int rem0  = (o0 & 511) + tx * 8;     // channel within chunk
    const int head  = rem0 >> 6;
    const int dd    = rem0 & 63;               // 8-aligned, stays in one head
    float* dst = (which == 0) ? g_q : ((which == 1) ? g_k : g_v);

#pragma unroll
    for (int i = 0; i < 8; i++) {
        int n = n0 + ty * 8 + i;
        size_t base = ((size_t)(b * P_ + head) * N_ + n) * D_ + dd;
        if (which == 1) {
            const float* rp = &g_rp[((size_t)head * N_ + n) * D_ + dd];
            float4 r0 = *(const float4*)&rp[0];
            float4 r1 = *(const float4*)&rp[4];
            acc[i][0] += r0.x; acc[i][1] += r0.y; acc[i][2] += r0.z; acc[i][3] += r0.w;
            acc[i][4] += r1.x; acc[i][5] += r1.y; acc[i][6] += r1.z; acc[i][7] += r1.w;
        }
        *(float4*)&dst[base]     = make_float4(acc[i][0], acc[i][1], acc[i][2], acc[i][3]);
        *(float4*)&dst[base + 4] = make_float4(acc[i][4], acc[i][5], acc[i][6], acc[i][7]);
    }
}

// ---------------- kernel 2: flash attention per (b,p), 64-query tiles ----------------
// No softmax scale (reference applies none). 256 threads, 4x4 microtiles.
#define PAD 68   // 64+4, keeps float4 alignment (68%4==0)

__global__ __launch_bounds__(256)
void attn_kernel(float* __restrict__ out) {
    extern __shared__ float sm[];
    float (*Qs)[PAD] = (float(*)[PAD])(sm);
    float (*Ks)[PAD] = (float(*)[PAD])(sm + 64 * PAD);
    float (*Vs)[PAD] = (float(*)[PAD])(sm + 2 * 64 * PAD);
    float (*Ps)[PAD] = (float(*)[PAD])(sm + 3 * 64 * PAD);

    const int b  = blockIdx.z;
    const int p  = blockIdx.y;
    const int n0 = blockIdx.x * 64;
    const int tid = threadIdx.x;
    const int tx = tid & 15, ty = tid >> 4;

    const size_t hb = (size_t)(b * P_ + p) * N_ * D_;

    // load Q tile [64][64]
#pragma unroll
    for (int r = 0; r < 4; r++) {
        int idx = tid + r * 256;            // 0..1023
        int row = idx >> 4, c4 = idx & 15;
        *(float4*)&Qs[row][c4 * 4] =
            *(const float4*)&g_q[hb + (size_t)(n0 + row) * D_ + c4 * 4];
    }

    float m_i[4], l_i[4], o_acc[4][4];
#pragma unroll
    for (int i = 0; i < 4; i++) {
        m_i[i] = -INFINITY; l_i[i] = 0.f;
#pragma unroll
        for (int j = 0; j < 4; j++) o_acc[i][j] = 0.f;
    }

    for (int kt = 0; kt < 16; kt++) {
        // load K', V tiles
#pragma unroll
        for (int r = 0; r < 4; r++) {
            int idx = tid + r * 256;
            int row = idx >> 4, c4 = idx & 15;
            size_t g = hb + (size_t)(kt * 64 + row) * D_ + c4 * 4;
            *(float4*)&Ks[row][c4 * 4] = *(const float4*)&g_k[g];
            *(float4*)&Vs[row][c4 * 4] = *(const float4*)&g_v[g];
        }
        __syncthreads();

        // S = Q K'^T  (4x4 per thread: rows ty*4+i, cols tx*4+j)
        float s[4][4];
#pragma unroll
        for (int i = 0; i < 4; i++)
#pragma unroll
            for (int j = 0; j < 4; j++) s[i][j] = 0.f;

#pragma unroll
        for (int kk = 0; kk < 64; kk += 4) {
            float4 a[4], bb[4];
#pragma unroll
            for (int i = 0; i < 4; i++) a[i]  = *(float4*)&Qs[ty * 4 + i][kk];
#pragma unroll
            for (int j = 0; j < 4; j++) bb[j] = *(float4*)&Ks[tx * 4 + j][kk];
#pragma unroll
            for (int i = 0; i < 4; i++)
#pragma unroll
                for (int j = 0; j < 4; j++)
                    s[i][j] += a[i].x * bb[j].x + a[i].y * bb[j].y +
                               a[i].z * bb[j].z + a[i].w * bb[j].w;
        }

        // online softmax (row reduce over 16 lanes sharing ty)
#pragma unroll
        for (int i = 0; i < 4; i++) {
            float rm = fmaxf(fmaxf(s[i][0], s[i][1]), fmaxf(s[i][2], s[i][3]));
#pragma unroll
            for (int msk = 8; msk >= 1; msk >>= 1)
                rm = fmaxf(rm, __shfl_xor_sync(0xffffffffu, rm, msk));
            float m_new = fmaxf(m_i[i], rm);
            float corr  = __expf(m_i[i] - m_new);
            float rs = 0.f;
#pragma unroll
            for (int j = 0; j < 4; j++) { s[i][j] = __expf(s[i][j] - m_new); rs += s[i][j]; }
#pragma unroll
            for (int msk = 8; msk >= 1; msk >>= 1)
                rs += __shfl_xor_sync(0xffffffffu, rs, msk);
            l_i[i] = l_i[i] * corr + rs;
            m_i[i] = m_new;
#pragma unroll
            for (int j = 0; j < 4; j++) o_acc[i][j] *= corr;
        }

        // stage P
#pragma unroll
        for (int i = 0; i < 4; i++)
            *(float4*)&Ps[ty * 4 + i][tx * 4] =
                make_float4(s[i][0], s[i][1], s[i][2], s[i][3]);
        __syncthreads();

        // O += P V   (rows ty*4+i = query, cols tx*4+j = d)
#pragma unroll
        for (int kk = 0; kk < 64; kk++) {
            float pr[4];
#pragma unroll
            for (int i = 0; i < 4; i++) pr[i] = Ps[ty * 4 + i][kk];
            float4 v4 = *(float4*)&Vs[kk][tx * 4];
#pragma unroll
            for (int i = 0; i < 4; i++) {
                o_acc[i][0] += pr[i] * v4.x;
                o_acc[i][1] += pr[i] * v4.y;
                o_acc[i][2] += pr[i] * v4.z;
                o_acc[i][3] += pr[i] * v4.w;
            }
        }
        __syncthreads();
    }

    // normalize, stage to smem, write transposed/coalesced: out[b, p*64+dd, n]
#pragma unroll
    for (int i = 0; i < 4; i++) {
        float inv = 1.f / l_i[i];
        *(float4*)&Ps[ty * 4 + i][tx * 4] =
            make_float4(o_acc[i][0] * inv, o_acc[i][1] * inv,
                        o_acc[i][2] * inv, o_acc[i][3] * inv);
    }
    __syncthreads();
#pragma unroll
    for (int r = 0; r < 16; r++) {
        int idx = tid + r * 256;          // 0..4095
        int dd = idx >> 6, nl = idx & 63;
        out[((size_t)(b * C_ + p * 64 + dd)) * N_ + n0 + nl] = Ps[nl][dd];
    }
}

// ---------------- launch ----------------
extern "C" void kernel_launch(void* const* d_in, const int* in_sizes, int n_in,
                              void* d_out, int out_size) {
    const float* x     = (const float*)d_in[0];   // [32,512,32,32]
    const float* qkv_w = (const float*)d_in[1];   // [1536,512]
    const float* h_pos = (const float*)d_in[2];   // [32,1,512]
    const float* w_pos = (const float*)d_in[3];   // [1,32,512]
    float* out = (float*)d_out;

    rp_kernel<<<(P_ * N_ * D_ + 255) / 256, 256>>>(h_pos, w_pos);

    dim3 g1(12, 8, B_);                 // o-tiles, n-tiles, batch
    qkv_kernel<<<g1, 256>>>(x, qkv_w);

    static int smem_set = 0;
    (void)smem_set;
    cudaFuncSetAttribute(attn_kernel,
                         cudaFuncAttributeMaxDynamicSharedMemorySize,
                         4 * 64 * PAD * (int)sizeof(float));
    dim3 g2(16, P_, B_);                // q-tiles, heads, batch
    attn_kernel<<<g2, 256, 4 * 64 * PAD * sizeof(float)>>>(out);
}

// round 6
// speedup vs baseline: 2.2339x; 2.2339x over previous
#include <cuda_runtime.h>
#include <math.h>

#define B_ 32
#define C_ 512
#define P_ 8
#define D_ 64
#define N_ 1024   // 32*32

// ---------------- scratch (__device__ globals: alloc-free rule) ----------------
__device__ float g_q[(size_t)B_ * P_ * N_ * D_];    // [b,p,n,d]
__device__ float g_k[(size_t)B_ * P_ * N_ * D_];    // [b,p,n,d] (k + rp folded)
__device__ float g_v[(size_t)B_ * P_ * N_ * D_];    // [b,p,n,d]
__device__ float g_qT[(size_t)B_ * P_ * D_ * N_];   // [b,p,d,n]
__device__ float g_kT[(size_t)B_ * P_ * D_ * N_];   // [b,p,d,n]
__device__ float g_rp[(size_t)P_ * N_ * D_];

// ---------------- packed f32x2 helpers ----------------
__device__ __forceinline__ unsigned long long pack2(float lo, float hi) {
    unsigned long long r;
    asm("mov.b64 %0, {%1, %2};" : "=l"(r) : "f"(lo), "f"(hi));
    return r;
}
__device__ __forceinline__ void unpack2(unsigned long long v, float& lo, float& hi) {
    asm("mov.b64 {%0, %1}, %2;" : "=f"(lo), "=f"(hi) : "l"(v));
}
__device__ __forceinline__ void fma2(unsigned long long& c,
                                     unsigned long long a, unsigned long long b) {
    asm("fma.rn.f32x2 %0, %1, %2, %0;" : "+l"(c) : "l"(a), "l"(b));
}
__device__ __forceinline__ void mul2(unsigned long long& c, unsigned long long a) {
    asm("mul.rn.f32x2 %0, %0, %1;" : "+l"(c) : "l"(a));
}

// ---------------- kernel 0: relative position table ----------------
__global__ void rp_kernel(const float* __restrict__ h_pos,
                          const float* __restrict__ w_pos) {
    int idx = blockIdx.x * blockDim.x + threadIdx.x;
    if (idx >= P_ * N_ * D_) return;
    int dd = idx & 63;
    int n  = (idx >> 6) & (N_ - 1);
    int p  = idx >> 16;
    int h  = n >> 5, w = n & 31;
    int c  = p * 64 + dd;
    g_rp[idx] = h_pos[h * C_ + c] + w_pos[w * C_ + c];
}

// ---------------- kernel 1: QKV GEMM with f32x2 ----------------
// Out[n,o] = sum_c X[b,c,n] * W[o,c]. Tile 128n x 128o, BK=16, 256 threads.
// Per-thread 8n x 8o; accumulators packed over o-pairs.
// Thread tx owns o-pairs at {2tx+32j, 2tx+1+32j}, j=0..3 (conflict-free LDS.64).
__global__ __launch_bounds__(256, 2)
void qkv_kernel(const float* __restrict__ x, const float* __restrict__ w) {
    __shared__ float AsD[16][264];   // X dup over n: [c][2n], 128 n -> 256 cols
    __shared__ float Bs[16][132];    // W: [c][o]

    const int b  = blockIdx.z;
    const int o0 = blockIdx.x * 128;
    const int n0 = blockIdx.y * 128;
    const int tid = threadIdx.x;
    const int tx = tid & 15, ty = tid >> 4;   // ty 0..15

    const float* xb = x + (size_t)b * C_ * N_;

    unsigned long long acc[8][4];
#pragma unroll
    for (int i = 0; i < 8; i++)
#pragma unroll
        for (int j = 0; j < 4; j++) acc[i][j] = 0ull;

    // prologue: load tile 0 into regs, store to smem
    float4 xa[2], wb[2];
    {
        const int k0 = 0;
#pragma unroll
        for (int pp = 0; pp < 2; pp++) {
            int kk = (tid >> 5) + pp * 8;
            int n4 = tid & 31;
            xa[pp] = *(const float4*)&xb[(size_t)(k0 + kk) * N_ + n0 + n4 * 4];
            int row = (tid >> 2) + pp * 64;
            int c4  = tid & 3;
            wb[pp] = *(const float4*)&w[(size_t)(o0 + row) * C_ + k0 + c4 * 4];
        }
#pragma unroll
        for (int pp = 0; pp < 2; pp++) {
            int kk = (tid >> 5) + pp * 8;
            int n4 = tid & 31;
            *(float4*)&AsD[kk][n4 * 8]     = make_float4(xa[pp].x, xa[pp].x, xa[pp].y, xa[pp].y);
            *(float4*)&AsD[kk][n4 * 8 + 4] = make_float4(xa[pp].z, xa[pp].z, xa[pp].w, xa[pp].w);
            int row = (tid >> 2) + pp * 64;
            int c4  = tid & 3;
            Bs[c4 * 4 + 0][row] = wb[pp].x;
            Bs[c4 * 4 + 1][row] = wb[pp].y;
            Bs[c4 * 4 + 2][row] = wb[pp].z;
            Bs[c4 * 4 + 3][row] = wb[pp].w;
        }
    }

    for (int t = 0; t < 32; t++) {
        __syncthreads();
        if (t < 31) {
            const int k0 = (t + 1) * 16;
#pragma unroll
            for (int pp = 0; pp < 2; pp++) {
                int kk = (tid >> 5) + pp * 8;
                int n4 = tid & 31;
                xa[pp] = *(const float4*)&xb[(size_t)(k0 + kk) * N_ + n0 + n4 * 4];
                int row = (tid >> 2) + pp * 64;
                int c4  = tid & 3;
                wb[pp] = *(const float4*)&w[(size_t)(o0 + row) * C_ + k0 + c4 * 4];
            }
        }
#pragma unroll
        for (int kk = 0; kk < 16; kk++) {
            ulonglong2 aA = *(ulonglong2*)&AsD[kk][16 * ty];
            ulonglong2 aB = *(ulonglong2*)&AsD[kk][16 * ty + 4];
            ulonglong2 aC = *(ulonglong2*)&AsD[kk][16 * ty + 8];
            ulonglong2 aD = *(ulonglong2*)&AsD[kk][16 * ty + 12];
            unsigned long long bd[4];
#pragma unroll
            for (int j = 0; j < 4; j++)
                bd[j] = *(unsigned long long*)&Bs[kk][2 * tx + 32 * j];
#pragma unroll
            for (int j = 0; j < 4; j++) {
                fma2(acc[0][j], aA.x, bd[j]);
                fma2(acc[1][j], aA.y, bd[j]);
                fma2(acc[2][j], aB.x, bd[j]);
                fma2(acc[3][j], aB.y, bd[j]);
                fma2(acc[4][j], aC.x, bd[j]);
                fma2(acc[5][j], aC.y, bd[j]);
                fma2(acc[6][j], aD.x, bd[j]);
                fma2(acc[7][j], aD.y, bd[j]);
            }
        }
        __syncthreads();
        if (t < 31) {
#pragma unroll
            for (int pp = 0; pp < 2; pp++) {
                int kk = (tid >> 5) + pp * 8;
                int n4 = tid & 31;
                *(float4*)&AsD[kk][n4 * 8]     = make_float4(xa[pp].x, xa[pp].x, xa[pp].y, xa[pp].y);
                *(float4*)&AsD[kk][n4 * 8 + 4] = make_float4(xa[pp].z, xa[pp].z, xa[pp].w, xa[pp].w);
                int row = (tid >> 2) + pp * 64;
                int c4  = tid & 3;
                Bs[c4 * 4 + 0][row] = wb[pp].x;
                Bs[c4 * 4 + 1][row] = wb[pp].y;
                Bs[c4 * 4 + 2][row] = wb[pp].z;
                Bs[c4 * 4 + 3][row] = wb[pp].w;
            }
        }
    }

    // epilogue -> g_q/g_k/g_v in [b,p,n,d]; k adds rp
    const int which = o0 >> 9;
    const int rem0  = (o0 & 511);
    float* dst = (which == 0) ? g_q : ((which == 1) ? g_k : g_v);

#pragma unroll
    for (int i = 0; i < 8; i++) {
        int n = n0 + ty * 8 + i;
#pragma unroll
        for (int j = 0; j < 4; j++) {
            int rem  = rem0 + 2 * tx + 32 * j;
            int head = rem >> 6;
            int dd   = rem & 63;
            float lo, hi;
            unpack2(acc[i][j], lo, hi);
            size_t base = ((size_t)(b * P_ + head) * N_ + n) * D_ + dd;
            if (which == 1) {
                float2 r = *(const float2*)&g_rp[((size_t)head * N_ + n) * D_ + dd];
                lo += r.x; hi += r.y;
            }
            *(float2*)&dst[base] = make_float2(lo, hi);
        }
    }
}

// ---------------- kernel 1.5: transpose q,k -> [b,p,d,n] ----------------
__global__ __launch_bounds__(256)
void trans_kernel() {
    __shared__ float t[32][33];
    const int z  = blockIdx.z;                 // bp 0..255
    const int wq = blockIdx.y >> 1;            // 0:q 1:k
    const int d0 = (blockIdx.y & 1) * 32;
    const int n0 = blockIdx.x * 32;
    const float* src = (wq ? g_k : g_q) + (size_t)z * N_ * D_;
    float* dst = (wq ? g_kT : g_qT) + (size_t)z * D_ * N_;

    const int r  = threadIdx.x >> 3;           // 0..31
    const int c4 = (threadIdx.x & 7) * 4;      // 0..28
    float4 v = *(const float4*)&src[(size_t)(n0 + r) * D_ + d0 + c4];
    t[r][c4] = v.x; t[r][c4 + 1] = v.y; t[r][c4 + 2] = v.z; t[r][c4 + 3] = v.w;
    __syncthreads();
    float4 o;
    o.x = t[c4 + 0][r]; o.y = t[c4 + 1][r]; o.z = t[c4 + 2][r]; o.w = t[c4 + 3][r];
    *(float4*)&dst[(size_t)(d0 + r) * N_ + n0 + c4] = o;
}

// ---------------- kernel 2: flash attention with f32x2 ----------------
// 128 threads, Br=64 queries, Bc=64 keys/tile. tx 0..15, ty 0..7.
// Thread owns queries ty*8..ty*8+7 (S: as 4 natural pairs from QsT),
// keys {tx+16j} (dup-pairs from KsD), output d = tx*4..tx*4+3 (2 pairs from Vs).
// smem: QsT[64][68] | KPs[64][132] (KsD in S phase, PsD in PV phase) | Vs[64][68]
#define SM_Q  (64 * 68)
#define SM_KP (64 * 132)
#define SM_V  (64 * 68)

__global__ __launch_bounds__(128, 3)
void attn_kernel(float* __restrict__ out) {
    extern __shared__ float sm[];
    float* QsT = sm;
    float* KPs = sm + SM_Q;
    float* Vs  = sm + SM_Q + SM_KP;

    const int b  = blockIdx.z;
    const int p  = blockIdx.y;
    const int n0 = blockIdx.x * 64;
    const int tid = threadIdx.x;
    const int tx = tid & 15, ty = tid >> 4;

    const size_t hbT = (size_t)(b * P_ + p) * D_ * N_;
    const size_t hbV = (size_t)(b * P_ + p) * N_ * D_;

    // Q fill: QsT[d][q]
#pragma unroll
    for (int r = 0; r < 8; r++) {
        int idx = tid + r * 128;
        int row = idx >> 4, c4 = (idx & 15) * 4;
        *(float4*)&QsT[row * 68 + c4] =
            *(const float4*)&g_qT[hbT + (size_t)row * N_ + n0 + c4];
    }

    float m_i[8], l_i[8];
    unsigned long long o2[8][2];
#pragma unroll
    for (int i = 0; i < 8; i++) {
        m_i[i] = -INFINITY; l_i[i] = 0.f; o2[i][0] = 0ull; o2[i][1] = 0ull;
    }

    for (int kt = 0; kt < 16; kt++) {
        __syncthreads();   // prev PV done with KPs/Vs
        // fill KsD (dup keys) and Vs
#pragma unroll
        for (int r = 0; r < 8; r++) {
            int idx = tid + r * 128;
            int row = idx >> 4, c4 = (idx & 15) * 4;
            float4 kv = *(const float4*)&g_kT[hbT + (size_t)row * N_ + kt * 64 + c4];
            *(float4*)&KPs[row * 132 + 2 * c4]     = make_float4(kv.x, kv.x, kv.y, kv.y);
            *(float4*)&KPs[row * 132 + 2 * c4 + 4] = make_float4(kv.z, kv.z, kv.w, kv.w);
            float4 vv = *(const float4*)&g_v[hbV + (size_t)(kt * 64 + row) * D_ + c4];
            *(float4*)&Vs[row * 68 + c4] = vv;
        }
        __syncthreads();

        // S = Q (K+rp)^T
        unsigned long long s2[4][4];
#pragma unroll
        for (int ip = 0; ip < 4; ip++)
#pragma unroll
            for (int j = 0; j < 4; j++) s2[ip][j] = 0ull;

#pragma unroll 4
        for (int kk = 0; kk < 64; kk++) {
            ulonglong2 aA = *(ulonglong2*)&QsT[kk * 68 + ty * 8];
            ulonglong2 aB = *(ulonglong2*)&QsT[kk * 68 + ty * 8 + 4];
            unsigned long long bd[4];
#pragma unroll
            for (int j = 0; j < 4; j++)
                bd[j] = *(unsigned long long*)&KPs[kk * 132 + 2 * (tx + 16 * j)];
#pragma unroll
            for (int j = 0; j < 4; j++) {
                fma2(s2[0][j], aA.x, bd[j]);
                fma2(s2[1][j], aA.y, bd[j]);
                fma2(s2[2][j], aB.x, bd[j]);
                fma2(s2[3][j], aB.y, bd[j]);
            }
        }

        float s[8][4];
#pragma unroll
        for (int ip = 0; ip < 4; ip++)
#pragma unroll
            for (int j = 0; j < 4; j++)
                unpack2(s2[ip][j], s[2 * ip][j], s[2 * ip + 1][j]);

        // online softmax (reduce across the 16 tx lanes)
#pragma unroll
        for (int i = 0; i < 8; i++) {
            float rm = fmaxf(fmaxf(s[i][0], s[i][1]), fmaxf(s[i][2], s[i][3]));
#pragma unroll
            for (int msk = 8; msk >= 1; msk >>= 1)
                rm = fmaxf(rm, __shfl_xor_sync(0xffffffffu, rm, msk));
            float m_new = fmaxf(m_i[i], rm);
            float corr  = __expf(m_i[i] - m_new);
            float rs = 0.f;
#pragma unroll
            for (int j = 0; j < 4; j++) { s[i][j] = __expf(s[i][j] - m_new); rs += s[i][j]; }
#pragma unroll
            for (int msk = 8; msk >= 1; msk >>= 1)
                rs += __shfl_xor_sync(0xffffffffu, rs, msk);
            l_i[i] = l_i[i] * corr + rs;
            m_i[i] = m_new;
            unsigned long long c2 = pack2(corr, corr);
            mul2(o2[i][0], c2);
            mul2(o2[i][1], c2);
        }

        __syncthreads();   // all warps done reading KsD
        // store duplicated P into KPs: PsD[q][2*key]
#pragma unroll
        for (int i = 0; i < 8; i++)
#pragma unroll
            for (int j = 0; j < 4; j++)
                *(float2*)&KPs[(ty * 8 + i) * 132 + 2 * (tx + 16 * j)] =
                    make_float2(s[i][j], s[i][j]);
        __syncthreads();

        // O += P V
#pragma unroll 2
        for (int kk2 = 0; kk2 < 32; kk2++) {
            ulonglong2 v0 = *(ulonglong2*)&Vs[(2 * kk2) * 68 + tx * 4];
            ulonglong2 v1 = *(ulonglong2*)&Vs[(2 * kk2 + 1) * 68 + tx * 4];
#pragma unroll
            for (int i = 0; i < 8; i++) {
                ulonglong2 p2 = *(ulonglong2*)&KPs[(ty * 8 + i) * 132 + 4 * kk2];
                fma2(o2[i][0], p2.x, v0.x);
                fma2(o2[i][1], p2.x, v0.y);
                fma2(o2[i][0], p2.y, v1.x);
                fma2(o2[i][1], p2.y, v1.y);
            }
        }
    }

    // normalize, stage, write transposed/coalesced: out[b, p*64+dd, n]
    __syncthreads();
    float* Os = KPs;   // [64][65]
#pragma unroll
    for (int i = 0; i < 8; i++) {
        float inv = 1.f / l_i[i];
        float a, bv, c, d;
        unpack2(o2[i][0], a, bv);
        unpack2(o2[i][1], c, d);
        int q = ty * 8 + i;
        Os[q * 65 + tx * 4 + 0] = a * inv;
        Os[q * 65 + tx * 4 + 1] = bv * inv;
        Os[q * 65 + tx * 4 + 2] = c * inv;
        Os[q * 65 + tx * 4 + 3] = d * inv;
    }
    __syncthreads();
#pragma unroll
    for (int r = 0; r < 32; r++) {
        int idx = tid + r * 128;
        int dd = idx >> 6, nl = idx & 63;
        out[((size_t)(b * C_ + p * 64 + dd)) * N_ + n0 + nl] = Os[nl * 65 + dd];
    }
}

// ---------------- launch ----------------
extern "C" void kernel_launch(void* const* d_in, const int* in_sizes, int n_in,
                              void* d_out, int out_size) {
    const float* x     = (const float*)d_in[0];
    const float* qkv_w = (const float*)d_in[1];
    const float* h_pos = (const float*)d_in[2];
    const float* w_pos = (const float*)d_in[3];
    float* out = (float*)d_out;

    rp_kernel<<<(P_ * N_ * D_ + 255) / 256, 256>>>(h_pos, w_pos);

    dim3 g1(12, 8, B_);
    qkv_kernel<<<g1, 256>>>(x, qkv_w);

    dim3 gt(32, 4, 256);
    trans_kernel<<<gt, 256>>>();

    const int attn_smem = (SM_Q + SM_KP + SM_V) * (int)sizeof(float);  // 68608
    cudaFuncSetAttribute(attn_kernel,
                         cudaFuncAttributeMaxDynamicSharedMemorySize, attn_smem);
    dim3 g2(16, P_, B_);
    attn_kernel<<<g2, 128, attn_smem>>>(out);
}

// round 8
// speedup vs baseline: 2.7545x; 1.2330x over previous
#include <cuda_runtime.h>
#include <math.h>

#define B_ 32
#define C_ 512
#define P_ 8
#define D_ 64
#define N_ 1024   // 32*32

// ---------------- scratch (__device__ globals: alloc-free rule) ----------------
__device__ float g_q[(size_t)B_ * P_ * N_ * D_];    // [b,p,n,d]
__device__ float g_k[(size_t)B_ * P_ * N_ * D_];    // [b,p,n,d] (k + rp folded)
__device__ float g_v[(size_t)B_ * P_ * N_ * D_];    // [b,p,n,d]
__device__ float g_qT[(size_t)B_ * P_ * D_ * N_];   // [b,p,d,n]
__device__ float g_kT[(size_t)B_ * P_ * D_ * N_];   // [b,p,d,n]
__device__ float g_rp[(size_t)P_ * N_ * D_];

// ---------------- packed f32x2 helpers ----------------
__device__ __forceinline__ unsigned long long pack2(float lo, float hi) {
    unsigned long long r;
    asm("mov.b64 %0, {%1, %2};" : "=l"(r) : "f"(lo), "f"(hi));
    return r;
}
__device__ __forceinline__ void unpack2(unsigned long long v, float& lo, float& hi) {
    asm("mov.b64 {%0, %1}, %2;" : "=f"(lo), "=f"(hi) : "l"(v));
}
__device__ __forceinline__ void fma2(unsigned long long& c,
                                     unsigned long long a, unsigned long long b) {
    asm("fma.rn.f32x2 %0, %1, %2, %0;" : "+l"(c) : "l"(a), "l"(b));
}
__device__ __forceinline__ void mul2(unsigned long long& c, unsigned long long a) {
    asm("mul.rn.f32x2 %0, %0, %1;" : "+l"(c) : "l"(a));
}

// ---------------- kernel 0: relative position table ----------------
__global__ void rp_kernel(const float* __restrict__ h_pos,
                          const float* __restrict__ w_pos) {
    int idx = blockIdx.x * blockDim.x + threadIdx.x;
    if (idx >= P_ * N_ * D_) return;
    int dd = idx & 63;
    int n  = (idx >> 6) & (N_ - 1);
    int p  = idx >> 16;
    int h  = n >> 5, w = n & 31;
    int c  = p * 64 + dd;
    g_rp[idx] = h_pos[h * C_ + c] + w_pos[w * C_ + c];
}

// ---------------- kernel 1: QKV GEMM with f32x2 (natural smem, register dup) ----------------
// Out[n,o] = sum_c X[b,c,n] * W[o,c]. Tile 128n x 128o, BK=16, 256 threads.
__global__ __launch_bounds__(256, 2)
void qkv_kernel(const float* __restrict__ x, const float* __restrict__ w) {
    __shared__ float As[16][132];   // X natural: [c][n]
    __shared__ float Bs[16][132];   // W: [c][o]

    const int b  = blockIdx.z;
    const int o0 = blockIdx.x * 128;
    const int n0 = blockIdx.y * 128;
    const int tid = threadIdx.x;
    const int tx = tid & 15, ty = tid >> 4;   // ty 0..15

    const float* xb = x + (size_t)b * C_ * N_;

    unsigned long long acc[8][4];
#pragma unroll
    for (int i = 0; i < 8; i++)
#pragma unroll
        for (int j = 0; j < 4; j++) acc[i][j] = 0ull;

    float4 xa[2], wb[2];
    // prologue: tile 0
    {
#pragma unroll
        for (int pp = 0; pp < 2; pp++) {
            int kk = (tid >> 5) + pp * 8;
            int n4 = tid & 31;
            xa[pp] = *(const float4*)&xb[(size_t)kk * N_ + n0 + n4 * 4];
            int row = (tid >> 2) + pp * 64;
            int c4  = tid & 3;
            wb[pp] = *(const float4*)&w[(size_t)(o0 + row) * C_ + c4 * 4];
        }
#pragma unroll
        for (int pp = 0; pp < 2; pp++) {
            int kk = (tid >> 5) + pp * 8;
            int n4 = tid & 31;
            *(float4*)&As[kk][n4 * 4] = xa[pp];
            int row = (tid >> 2) + pp * 64;
            int c4  = tid & 3;
            Bs[c4 * 4 + 0][row] = wb[pp].x;
            Bs[c4 * 4 + 1][row] = wb[pp].y;
            Bs[c4 * 4 + 2][row] = wb[pp].z;
            Bs[c4 * 4 + 3][row] = wb[pp].w;
        }
    }

    for (int t = 0; t < 32; t++) {
        __syncthreads();
        if (t < 31) {
            const int k0 = (t + 1) * 16;
#pragma unroll
            for (int pp = 0; pp < 2; pp++) {
                int kk = (tid >> 5) + pp * 8;
                int n4 = tid & 31;
                xa[pp] = *(const float4*)&xb[(size_t)(k0 + kk) * N_ + n0 + n4 * 4];
                int row = (tid >> 2) + pp * 64;
                int c4  = tid & 3;
                wb[pp] = *(const float4*)&w[(size_t)(o0 + row) * C_ + k0 + c4 * 4];
            }
        }
#pragma unroll
        for (int kk = 0; kk < 16; kk++) {
            float4 a0 = *(float4*)&As[kk][ty * 8];
            float4 a1 = *(float4*)&As[kk][ty * 8 + 4];
            unsigned long long ad[8];
            ad[0] = pack2(a0.x, a0.x); ad[1] = pack2(a0.y, a0.y);
            ad[2] = pack2(a0.z, a0.z); ad[3] = pack2(a0.w, a0.w);
            ad[4] = pack2(a1.x, a1.x); ad[5] = pack2(a1.y, a1.y);
            ad[6] = pack2(a1.z, a1.z); ad[7] = pack2(a1.w, a1.w);
            unsigned long long bd[4];
#pragma unroll
            for (int j = 0; j < 4; j++)
                bd[j] = *(unsigned long long*)&Bs[kk][2 * tx + 32 * j];
#pragma unroll
            for (int j = 0; j < 4; j++)
#pragma unroll
                for (int i = 0; i < 8; i++)
                    fma2(acc[i][j], ad[i], bd[j]);
        }
        __syncthreads();
        if (t < 31) {
#pragma unroll
            for (int pp = 0; pp < 2; pp++) {
                int kk = (tid >> 5) + pp * 8;
                int n4 = tid & 31;
                *(float4*)&As[kk][n4 * 4] = xa[pp];
                int row = (tid >> 2) + pp * 64;
                int c4  = tid & 3;
                Bs[c4 * 4 + 0][row] = wb[pp].x;
                Bs[c4 * 4 + 1][row] = wb[pp].y;
                Bs[c4 * 4 + 2][row] = wb[pp].z;
                Bs[c4 * 4 + 3][row] = wb[pp].w;
            }
        }
    }

    // epilogue -> g_q/g_k/g_v in [b,p,n,d]; k adds rp
    const int which = o0 >> 9;
    const int rem0  = (o0 & 511);
    float* dst = (which == 0) ? g_q : ((which == 1) ? g_k : g_v);

#pragma unroll
    for (int i = 0; i < 8; i++) {
        int n = n0 + ty * 8 + i;
#pragma unroll
        for (int j = 0; j < 4; j++) {
            int rem  = rem0 + 2 * tx + 32 * j;
            int head = rem >> 6;
            int dd   = rem & 63;
            float lo, hi;
            unpack2(acc[i][j], lo, hi);
            size_t base = ((size_t)(b * P_ + head) * N_ + n) * D_ + dd;
            if (which == 1) {
                float2 r = *(const float2*)&g_rp[((size_t)head * N_ + n) * D_ + dd];
                lo += r.x; hi += r.y;
            }
            *(float2*)&dst[base] = make_float2(lo, hi);
        }
    }
}

// ---------------- kernel 1.5: transpose q,k -> [b,p,d,n] ----------------
__global__ __launch_bounds__(256)
void trans_kernel() {
    __shared__ float t[32][33];
    const int z  = blockIdx.z;                 // bp 0..255
    const int wq = blockIdx.y >> 1;            // 0:q 1:k
    const int d0 = (blockIdx.y & 1) * 32;
    const int n0 = blockIdx.x * 32;
    const float* src = (wq ? g_k : g_q) + (size_t)z * N_ * D_;
    float* dst = (wq ? g_kT : g_qT) + (size_t)z * D_ * N_;

    const int r  = threadIdx.x >> 3;           // 0..31
    const int c4 = (threadIdx.x & 7) * 4;      // 0..28
    float4 v = *(const float4*)&src[(size_t)(n0 + r) * D_ + d0 + c4];
    t[r][c4] = v.x; t[r][c4 + 1] = v.y; t[r][c4 + 2] = v.z; t[r][c4 + 3] = v.w;
    __syncthreads();
    float4 o;
    o.x = t[c4 + 0][r]; o.y = t[c4 + 1][r]; o.z = t[c4 + 2][r]; o.w = t[c4 + 3][r];
    *(float4*)&dst[(size_t)(d0 + r) * N_ + n0 + c4] = o;
}

// ---------------- kernel 2: flash attention, f32x2, natural smem + register dup ----------------
// 128 threads, Br=64 queries, Bc=64 keys. tx 0..15, ty 0..7.
// smem: QsT[64][68] | KPs[64][68] (K natural [d][key] in S phase, P natural [q][key] in PV) | Vs[64][68]
#define SM_T (64 * 68)

__global__ __launch_bounds__(128, 3)
void attn_kernel(float* __restrict__ out) {
    extern __shared__ float sm[];
    float* QsT = sm;
    float* KPs = sm + SM_T;
    float* Vs  = sm + 2 * SM_T;

    const int b  = blockIdx.z;
    const int p  = blockIdx.y;
    const int n0 = blockIdx.x * 64;
    const int tid = threadIdx.x;
    const int tx = tid & 15, ty = tid >> 4;

    const size_t hbT = (size_t)(b * P_ + p) * D_ * N_;
    const size_t hbV = (size_t)(b * P_ + p) * N_ * D_;

    // Q fill: QsT[d][q]
#pragma unroll
    for (int r = 0; r < 8; r++) {
        int idx = tid + r * 128;
        int row = idx >> 4, c4 = (idx & 15) * 4;
        *(float4*)&QsT[row * 68 + c4] =
            *(const float4*)&g_qT[hbT + (size_t)row * N_ + n0 + c4];
    }

    float m_i[8], l_i[8];
    unsigned long long o2[8][2];
#pragma unroll
    for (int i = 0; i < 8; i++) {
        m_i[i] = -INFINITY; l_i[i] = 0.f; o2[i][0] = 0ull; o2[i][1] = 0ull;
    }

    for (int kt = 0; kt < 16; kt++) {
        __syncthreads();   // prev PV done with KPs/Vs
        // fill Ks (natural [d][key]) and Vs ([key][d])
#pragma unroll
        for (int r = 0; r < 8; r++) {
            int idx = tid + r * 128;
            int row = idx >> 4, c4 = (idx & 15) * 4;
            float4 kv = *(const float4*)&g_kT[hbT + (size_t)row * N_ + kt * 64 + c4];
            *(float4*)&KPs[row * 68 + c4] = kv;
            float4 vv = *(const float4*)&g_v[hbV + (size_t)(kt * 64 + row) * D_ + c4];
            *(float4*)&Vs[row * 68 + c4] = vv;
        }
        __syncthreads();

        // S = Q (K+rp)^T : thread -> queries ty*8..+7 (natural pairs), keys tx+16j
        unsigned long long s2[4][4];
#pragma unroll
        for (int ip = 0; ip < 4; ip++)
#pragma unroll
            for (int j = 0; j < 4; j++) s2[ip][j] = 0ull;

#pragma unroll 4
        for (int kk = 0; kk < 64; kk++) {
            ulonglong2 aA = *(ulonglong2*)&QsT[kk * 68 + ty * 8];
            ulonglong2 aB = *(ulonglong2*)&QsT[kk * 68 + ty * 8 + 4];
            unsigned long long bd[4];
#pragma unroll
            for (int j = 0; j < 4; j++) {
                float kf = KPs[kk * 68 + tx + 16 * j];
                bd[j] = pack2(kf, kf);
            }
#pragma unroll
            for (int j = 0; j < 4; j++) {
                fma2(s2[0][j], aA.x, bd[j]);
                fma2(s2[1][j], aA.y, bd[j]);
                fma2(s2[2][j], aB.x, bd[j]);
                fma2(s2[3][j], aB.y, bd[j]);
            }
        }

        float s[8][4];
#pragma unroll
        for (int ip = 0; ip < 4; ip++)
#pragma unroll
            for (int j = 0; j < 4; j++)
                unpack2(s2[ip][j], s[2 * ip][j], s[2 * ip + 1][j]);

        // online softmax (reduce across the 16 tx lanes)
#pragma unroll
        for (int i = 0; i < 8; i++) {
            float rm = fmaxf(fmaxf(s[i][0], s[i][1]), fmaxf(s[i][2], s[i][3]));
#pragma unroll
            for (int msk = 8; msk >= 1; msk >>= 1)
                rm = fmaxf(rm, __shfl_xor_sync(0xffffffffu, rm, msk));
            float m_new = fmaxf(m_i[i], rm);
            float corr  = __expf(m_i[i] - m_new);
            float rs = 0.f;
#pragma unroll
            for (int j = 0; j < 4; j++) { s[i][j] = __expf(s[i][j] - m_new); rs += s[i][j]; }
#pragma unroll
            for (int msk = 8; msk >= 1; msk >>= 1)
                rs += __shfl_xor_sync(0xffffffffu, rs, msk);
            l_i[i] = l_i[i] * corr + rs;
            m_i[i] = m_new;
            unsigned long long c2 = pack2(corr, corr);
            mul2(o2[i][0], c2);
            mul2(o2[i][1], c2);
        }

        __syncthreads();   // all warps done reading Ks
        // store natural P: Ps[q][key]
#pragma unroll
        for (int i = 0; i < 8; i++)
#pragma unroll
            for (int j = 0; j < 4; j++)
                KPs[(ty * 8 + i) * 68 + tx + 16 * j] = s[i][j];
        __syncthreads();

        // O += P V : keys in groups of 4 (float4 P read + register dup)
#pragma unroll 2
        for (int kk4 = 0; kk4 < 16; kk4++) {
            ulonglong2 v0 = *(ulonglong2*)&Vs[(4 * kk4 + 0) * 68 + tx * 4];
            ulonglong2 v1 = *(ulonglong2*)&Vs[(4 * kk4 + 1) * 68 + tx * 4];
            ulonglong2 v2 = *(ulonglong2*)&Vs[(4 * kk4 + 2) * 68 + tx * 4];
            ulonglong2 v3 = *(ulonglong2*)&Vs[(4 * kk4 + 3) * 68 + tx * 4];
#pragma unroll
            for (int i = 0; i < 8; i++) {
                float4 pf = *(float4*)&KPs[(ty * 8 + i) * 68 + 4 * kk4];
                unsigned long long p0 = pack2(pf.x, pf.x);
                unsigned long long p1 = pack2(pf.y, pf.y);
                unsigned long long p2 = pack2(pf.z, pf.z);
                unsigned long long p3 = pack2(pf.w, pf.w);
                fma2(o2[i][0], p0, v0.x); fma2(o2[i][1], p0, v0.y);
                fma2(o2[i][0], p1, v1.x); fma2(o2[i][1], p1, v1.y);
                fma2(o2[i][0], p2, v2.x); fma2(o2[i][1], p2, v2.y);
                fma2(o2[i][0], p3, v3.x); fma2(o2[i][1], p3, v3.y);
            }
        }
    }

    // normalize, stage, write transposed/coalesced: out[b, p*64+dd, n]
    __syncthreads();
    float* Os = KPs;   // [64][65]
#pragma unroll
    for (int i = 0; i < 8; i++) {
        float inv = 1.f / l_i[i];
        float a, bv, c, d;
        unpack2(o2[i][0], a, bv);
        unpack2(o2[i][1], c, d);
        int q = ty * 8 + i;
        Os[q * 65 + tx * 4 + 0] = a * inv;
        Os[q * 65 + tx * 4 + 1] = bv * inv;
        Os[q * 65 + tx * 4 + 2] = c * inv;
        Os[q * 65 + tx * 4 + 3] = d * inv;
    }
    __syncthreads();
#pragma unroll
    for (int r = 0; r < 32; r++) {
        int idx = tid + r * 128;
        int dd = idx >> 6, nl = idx & 63;
        out[((size_t)(b * C_ + p * 64 + dd)) * N_ + n0 + nl] = Os[nl * 65 + dd];
    }
}

// ---------------- launch ----------------
extern "C" void kernel_launch(void* const* d_in, const int* in_sizes, int n_in,
                              void* d_out, int out_size) {
    const float* x     = (const float*)d_in[0];
    const float* qkv_w = (const float*)d_in[1];
    const float* h_pos = (const float*)d_in[2];
    const float* w_pos = (const float*)d_in[3];
    float* out = (float*)d_out;

    rp_kernel<<<(P_ * N_ * D_ + 255) / 256, 256>>>(h_pos, w_pos);

    dim3 g1(12, 8, B_);
    qkv_kernel<<<g1, 256>>>(x, qkv_w);

    dim3 gt(32, 4, 256);
    trans_kernel<<<gt, 256>>>();

    const int attn_smem = 3 * SM_T * (int)sizeof(float);  // 52224
    cudaFuncSetAttribute(attn_kernel,
                         cudaFuncAttributeMaxDynamicSharedMemorySize, attn_smem);
    dim3 g2(16, P_, B_);
    attn_kernel<<<g2, 128, attn_smem>>>(out);
}

// round 10
// speedup vs baseline: 3.3863x; 1.2294x over previous
#include <cuda_runtime.h>
#include <cuda_bf16.h>
#include <math.h>
#include <cstdint>

#define B_ 32
#define C_ 512
#define P_ 8
#define D_ 64
#define N_ 1024   // 32*32

// ---------------- scratch (__device__ globals: alloc-free rule) ----------------
__device__ float g_qT[(size_t)B_ * P_ * D_ * N_];          // [b,p,d,n]
__device__ float g_kT[(size_t)B_ * P_ * D_ * N_];          // [b,p,d,n] (k + rp folded)
__device__ float g_v [(size_t)B_ * P_ * N_ * D_];          // [b,p,n,d]
__device__ float g_rpT[(size_t)P_ * D_ * N_];              // [p,d,n]
__device__ __nv_bfloat16 g_xh[(size_t)B_ * N_ * C_];       // x^T hi  [b,n,c]
__device__ __nv_bfloat16 g_xl[(size_t)B_ * N_ * C_];       // x^T lo
__device__ __nv_bfloat16 g_wh[(size_t)3 * C_ * C_];        // w hi [o,c]
__device__ __nv_bfloat16 g_wl[(size_t)3 * C_ * C_];        // w lo

// ---------------- packed f32x2 helpers ----------------
__device__ __forceinline__ unsigned long long pack2(float lo, float hi) {
    unsigned long long r;
    asm("mov.b64 %0, {%1, %2};" : "=l"(r) : "f"(lo), "f"(hi));
    return r;
}
__device__ __forceinline__ void unpack2(unsigned long long v, float& lo, float& hi) {
    asm("mov.b64 {%0, %1}, %2;" : "=f"(lo), "=f"(hi) : "l"(v));
}
__device__ __forceinline__ void fma2(unsigned long long& c,
                                     unsigned long long a, unsigned long long b) {
    asm("fma.rn.f32x2 %0, %1, %2, %0;" : "+l"(c) : "l"(a), "l"(b));
}
__device__ __forceinline__ void mul2(unsigned long long& c, unsigned long long a) {
    asm("mul.rn.f32x2 %0, %0, %1;" : "+l"(c) : "l"(a));
}

// ---------------- warp-MMA helpers (baseline ISA: sm_80+) ----------------
__device__ __forceinline__ uint32_t smem_u32(const void* p) {
    uint32_t a;
    asm("{ .reg .u64 t; cvta.to.shared.u64 t, %1; cvt.u32.u64 %0, t; }" : "=r"(a) : "l"(p));
    return a;
}
__device__ __forceinline__ void ldsm4(uint32_t a, uint32_t r[4]) {
    asm volatile("ldmatrix.sync.aligned.m8n8.x4.shared.b16 {%0,%1,%2,%3}, [%4];"
        : "=r"(r[0]), "=r"(r[1]), "=r"(r[2]), "=r"(r[3]) : "r"(a));
}
__device__ __forceinline__ void ldsm2(uint32_t a, uint32_t r[2]) {
    asm volatile("ldmatrix.sync.aligned.m8n8.x2.shared.b16 {%0,%1}, [%2];"
        : "=r"(r[0]), "=r"(r[1]) : "r"(a));
}
__device__ __forceinline__ void mma16816(float c[4], const uint32_t a[4], const uint32_t b[2]) {
    asm volatile("mma.sync.aligned.m16n8k16.row.col.f32.bf16.bf16.f32 "
        "{%0,%1,%2,%3}, {%4,%5,%6,%7}, {%8,%9}, {%0,%1,%2,%3};"
        : "+f"(c[0]), "+f"(c[1]), "+f"(c[2]), "+f"(c[3])
        : "r"(a[0]), "r"(a[1]), "r"(a[2]), "r"(a[3]), "r"(b[0]), "r"(b[1]));
}
__device__ __forceinline__ void cpa16(uint32_t s, const void* g) {
    asm volatile("cp.async.cg.shared.global [%0], [%1], 16;" :: "r"(s), "l"(g));
}
#define CP_COMMIT()  asm volatile("cp.async.commit_group;" ::: "memory")
#define CP_WAIT(n)   asm volatile("cp.async.wait_group %0;" :: "n"(n) : "memory")

// ---------------- kernel 0: transposed relative position table ----------------
__global__ void rpT_kernel(const float* __restrict__ h_pos,
                           const float* __restrict__ w_pos) {
    int idx = blockIdx.x * blockDim.x + threadIdx.x;
    if (idx >= P_ * D_ * N_) return;
    int n = idx & (N_ - 1);
    int d = (idx >> 10) & 63;
    int p = idx >> 16;
    int c = p * 64 + d;
    g_rpT[idx] = h_pos[(n >> 5) * C_ + c] + w_pos[(n & 31) * C_ + c];
}

// ---------------- kernel 0b: split+transpose X -> bf16 hi/lo [b,n,c] ----------------
__global__ __launch_bounds__(256)
void split_x_kernel(const float* __restrict__ x) {
    __shared__ float ts[32][33];
    const int b  = blockIdx.z;
    const int c0 = blockIdx.y * 32;
    const int n0 = blockIdx.x * 32;
    const int t = threadIdx.x;
    const int r = t >> 3, q4 = (t & 7) * 4;
    float4 v = *(const float4*)&x[((size_t)b * C_ + c0 + r) * N_ + n0 + q4];
    ts[r][q4] = v.x; ts[r][q4 + 1] = v.y; ts[r][q4 + 2] = v.z; ts[r][q4 + 3] = v.w;
    __syncthreads();
    ushort4 hi, lo;
    float f[4];
#pragma unroll
    for (int i = 0; i < 4; i++) f[i] = ts[q4 + i][r];
    __nv_bfloat16 h0 = __float2bfloat16(f[0]), h1 = __float2bfloat16(f[1]);
    __nv_bfloat16 h2 = __float2bfloat16(f[2]), h3 = __float2bfloat16(f[3]);
    hi.x = __bfloat16_as_ushort(h0); hi.y = __bfloat16_as_ushort(h1);
    hi.z = __bfloat16_as_ushort(h2); hi.w = __bfloat16_as_ushort(h3);
    lo.x = __bfloat16_as_ushort(__float2bfloat16(f[0] - __bfloat162float(h0)));
    lo.y = __bfloat16_as_ushort(__float2bfloat16(f[1] - __bfloat162float(h1)));
    lo.z = __bfloat16_as_ushort(__float2bfloat16(f[2] - __bfloat162float(h2)));
    lo.w = __bfloat16_as_ushort(__float2bfloat16(f[3] - __bfloat162float(h3)));
    size_t o = ((size_t)b * N_ + n0 + r) * C_ + c0 + q4;
    *(ushort4*)&g_xh[o] = hi;
    *(ushort4*)&g_xl[o] = lo;
}

// ---------------- kernel 0c: split W -> bf16 hi/lo [o,c] ----------------
__global__ void split_w_kernel(const float* __restrict__ w) {
    int f4 = blockIdx.x * blockDim.x + threadIdx.x;
    if (f4 >= 3 * C_ * C_ / 4) return;
    float4 v = ((const float4*)w)[f4];
    ushort4 hi, lo;
    __nv_bfloat16 h0 = __float2bfloat16(v.x), h1 = __float2bfloat16(v.y);
    __nv_bfloat16 h2 = __float2bfloat16(v.z), h3 = __float2bfloat16(v.w);
    hi.x = __bfloat16_as_ushort(h0); hi.y = __bfloat16_as_ushort(h1);
    hi.z = __bfloat16_as_ushort(h2); hi.w = __bfloat16_as_ushort(h3);
    lo.x = __bfloat16_as_ushort(__float2bfloat16(v.x - __bfloat162float(h0)));
    lo.y = __bfloat16_as_ushort(__float2bfloat16(v.y - __bfloat162float(h1)));
    lo.z = __bfloat16_as_ushort(__float2bfloat16(v.z - __bfloat162float(h2)));
    lo.w = __bfloat16_as_ushort(__float2bfloat16(v.w - __bfloat162float(h3)));
    ((ushort4*)g_wh)[f4] = hi;
    ((ushort4*)g_wl)[f4] = lo;
}

// ---------------- kernel 1: QKV GEMM via mma.sync bf16 split (3-term) ----------------
// q/k blocks (ob 0..7): D[o][n] = W X  -> write d-major g_qT/g_kT (+rp for k)
// v  blocks (ob 8..11): D[n][o] = X W  -> write g_v [p,n,d] directly
#define TILE_B 18432u           // 128 rows * 144 B (72 bf16, pad 8)
#define BUF_B  (4u * TILE_B)    // Wh | Wl | Xh | Xl
#define QKV_SMEM (2 * 4 * 18432)

__global__ __launch_bounds__(256)
void qkv_mma_kernel() {
    extern __shared__ char dynsm[];
    const int b  = blockIdx.z;
    const int nt = blockIdx.y;
    const int ob = blockIdx.x;
    const int o0 = ob * 128;
    const int tid = threadIdx.x;
    const int lane = tid & 31, wid = tid >> 5;
    const int wm = wid & 3, wn = wid >> 2;   // 4 (M) x 2 (N) warps

    const uint32_t sb = smem_u32(dynsm);
    const bool isv = (ob >= 8);

    const __nv_bfloat16* wh = g_wh + (size_t)o0 * C_;
    const __nv_bfloat16* wl = g_wl + (size_t)o0 * C_;
    const __nv_bfloat16* xh = g_xh + ((size_t)b * N_ + nt * 128) * C_;
    const __nv_bfloat16* xl = g_xl + ((size_t)b * N_ + nt * 128) * C_;

    auto issue = [&](int ch) {
        const int kc0 = ch * 64;
        const uint32_t buf = sb + (uint32_t)(ch & 1) * BUF_B;
#pragma unroll
        for (int j = 0; j < 4; j++) {
            int flat = tid + j * 256;          // 0..1023
            int row = flat >> 3, c8 = flat & 7;
            uint32_t so = (uint32_t)(row * 144 + c8 * 16);
            size_t go = (size_t)row * C_ + kc0 + c8 * 8;
            cpa16(buf + 0 * TILE_B + so, wh + go);
            cpa16(buf + 1 * TILE_B + so, wl + go);
            cpa16(buf + 2 * TILE_B + so, xh + go);
            cpa16(buf + 3 * TILE_B + so, xl + go);
        }
    };

    float acc[2][8][4];
#pragma unroll
    for (int ma = 0; ma < 2; ma++)
#pragma unroll
        for (int na = 0; na < 8; na++)
#pragma unroll
            for (int q = 0; q < 4; q++) acc[ma][na][q] = 0.f;

    issue(0); CP_COMMIT();
    for (int ch = 0; ch < 8; ch++) {
        if (ch < 7) { issue(ch + 1); CP_COMMIT(); CP_WAIT(1); }
        else        { CP_WAIT(0); }
        __syncthreads();
        const uint32_t buf = sb + (uint32_t)(ch & 1) * BUF_B;
        const uint32_t Ah = buf + (isv ? 2 * TILE_B : 0);
        const uint32_t Al = Ah + TILE_B;
        const uint32_t Bh = buf + (isv ? 0 : 2 * TILE_B);
        const uint32_t Bl = Bh + TILE_B;
#pragma unroll
        for (int ks = 0; ks < 4; ks++) {
            const int k0 = ks * 16;
            uint32_t ah[2][4], al[2][4];
#pragma unroll
            for (int ma = 0; ma < 2; ma++) {
                uint32_t aoff = (uint32_t)((wm * 32 + ma * 16 + (lane & 15)) * 144 +
                                           k0 * 2 + (lane >> 4) * 16);
                ldsm4(Ah + aoff, ah[ma]);
                ldsm4(Al + aoff, al[ma]);
            }
#pragma unroll
            for (int na = 0; na < 8; na++) {
                uint32_t boff = (uint32_t)((wn * 64 + na * 8 + (lane & 7)) * 144 +
                                           k0 * 2 + ((lane >> 3) & 1) * 16);
                uint32_t bh[2], bl[2];
                ldsm2(Bh + boff, bh);
                ldsm2(Bl + boff, bl);
#pragma unroll
                for (int ma = 0; ma < 2; ma++) {
                    mma16816(acc[ma][na], ah[ma], bh);
                    mma16816(acc[ma][na], ah[ma], bl);
                    mma16816(acc[ma][na], al[ma], bh);
                }
            }
        }
        __syncthreads();
    }

    // ---- epilogue ----
    const int which = o0 >> 9;                 // 0=q 1=k 2=v
    if (!isv) {
        float* dst = which ? g_kT : g_qT;
#pragma unroll
        for (int ma = 0; ma < 2; ma++) {
#pragma unroll
            for (int half = 0; half < 2; half++) {
                int oc = (o0 & 511) + wm * 32 + ma * 16 + (lane >> 2) + half * 8;
                int p = oc >> 6, d = oc & 63;
                size_t rowbase = ((size_t)(b * P_ + p) * D_ + d) * N_;
                size_t rpbase  = ((size_t)p * D_ + d) * N_;
#pragma unroll
                for (int na = 0; na < 8; na++) {
                    int col = nt * 128 + wn * 64 + na * 8 + (lane & 3) * 2;
                    float2 c2 = make_float2(acc[ma][na][half * 2], acc[ma][na][half * 2 + 1]);
                    if (which == 1) {
                        float2 r = *(const float2*)&g_rpT[rpbase + col];
                        c2.x += r.x; c2.y += r.y;
                    }
                    *(float2*)&dst[rowbase + col] = c2;
                }
            }
        }
    } else {
#pragma unroll
        for (int ma = 0; ma < 2; ma++) {
#pragma unroll
            for (int half = 0; half < 2; half++) {
                int nrow = nt * 128 + wm * 32 + ma * 16 + (lane >> 2) + half * 8;
#pragma unroll
                for (int na = 0; na < 8; na++) {
                    int oc = (o0 & 511) + wn * 64 + na * 8 + (lane & 3) * 2;
                    int p = oc >> 6, d = oc & 63;
                    *(float2*)&g_v[((size_t)(b * P_ + p) * N_ + nrow) * D_ + d] =
                        make_float2(acc[ma][na][half * 2], acc[ma][na][half * 2 + 1]);
                }
            }
        }
    }
}

// ---------------- kernel 2: flash attention, f32x2 (unchanged R8 winner) ----------------
#define SM_T (64 * 68)

__global__ __launch_bounds__(128, 3)
void attn_kernel(float* __restrict__ out) {
    extern __shared__ float sm[];
    float* QsT = sm;
    float* KPs = sm + SM_T;
    float* Vs  = sm + 2 * SM_T;

    const int b  = blockIdx.z;
    const int p  = blockIdx.y;
    const int n0 = blockIdx.x * 64;
    const int tid = threadIdx.x;
    const int tx = tid & 15, ty = tid >> 4;

    const size_t hbT = (size_t)(b * P_ + p) * D_ * N_;
    const size_t hbV = (size_t)(b * P_ + p) * N_ * D_;

#pragma unroll
    for (int r = 0; r < 8; r++) {
        int idx = tid + r * 128;
        int row = idx >> 4, c4 = (idx & 15) * 4;
        *(float4*)&QsT[row * 68 + c4] =
            *(const float4*)&g_qT[hbT + (size_t)row * N_ + n0 + c4];
    }

    float m_i[8], l_i[8];
    unsigned long long o2[8][2];
#pragma unroll
    for (int i = 0; i < 8; i++) {
        m_i[i] = -INFINITY; l_i[i] = 0.f; o2[i][0] = 0ull; o2[i][1] = 0ull;
    }

    for (int kt = 0; kt < 16; kt++) {
        __syncthreads();
#pragma unroll
        for (int r = 0; r < 8; r++) {
            int idx = tid + r * 128;
            int row = idx >> 4, c4 = (idx & 15) * 4;
            float4 kv = *(const float4*)&g_kT[hbT + (size_t)row * N_ + kt * 64 + c4];
            *(float4*)&KPs[row * 68 + c4] = kv;
            float4 vv = *(const float4*)&g_v[hbV + (size_t)(kt * 64 + row) * D_ + c4];
            *(float4*)&Vs[row * 68 + c4] = vv;
        }
        __syncthreads();

        unsigned long long s2[4][4];
#pragma unroll
        for (int ip = 0; ip < 4; ip++)
#pragma unroll
            for (int j = 0; j < 4; j++) s2[ip][j] = 0ull;

#pragma unroll 4
        for (int kk = 0; kk < 64; kk++) {
            ulonglong2 aA = *(ulonglong2*)&QsT[kk * 68 + ty * 8];
            ulonglong2 aB = *(ulonglong2*)&QsT[kk * 68 + ty * 8 + 4];
            unsigned long long bd[4];
#pragma unroll
            for (int j = 0; j < 4; j++) {
                float kf = KPs[kk * 68 + tx + 16 * j];
                bd[j] = pack2(kf, kf);
            }
#pragma unroll
            for (int j = 0; j < 4; j++) {
                fma2(s2[0][j], aA.x, bd[j]);
                fma2(s2[1][j], aA.y, bd[j]);
                fma2(s2[2][j], aB.x, bd[j]);
                fma2(s2[3][j], aB.y, bd[j]);
            }
        }

        float s[8][4];
#pragma unroll
        for (int ip = 0; ip < 4; ip++)
#pragma unroll
            for (int j = 0; j < 4; j++)
                unpack2(s2[ip][j], s[2 * ip][j], s[2 * ip + 1][j]);

#pragma unroll
        for (int i = 0; i < 8; i++) {
            float rm = fmaxf(fmaxf(s[i][0], s[i][1]), fmaxf(s[i][2], s[i][3]));
#pragma unroll
            for (int msk = 8; msk >= 1; msk >>= 1)
                rm = fmaxf(rm, __shfl_xor_sync(0xffffffffu, rm, msk));
            float m_new = fmaxf(m_i[i], rm);
            float corr  = __expf(m_i[i] - m_new);
            float rs = 0.f;
#pragma unroll
            for (int j = 0; j < 4; j++) { s[i][j] = __expf(s[i][j] - m_new); rs += s[i][j]; }
#pragma unroll
            for (int msk = 8; msk >= 1; msk >>= 1)
                rs += __shfl_xor_sync(0xffffffffu, rs, msk);
            l_i[i] = l_i[i] * corr + rs;
            m_i[i] = m_new;
            unsigned long long c2 = pack2(corr, corr);
            mul2(o2[i][0], c2);
            mul2(o2[i][1], c2);
        }

        __syncthreads();
#pragma unroll
        for (int i = 0; i < 8; i++)
#pragma unroll
            for (int j = 0; j < 4; j++)
                KPs[(ty * 8 + i) * 68 + tx + 16 * j] = s[i][j];
        __syncthreads();

#pragma unroll 2
        for (int kk4 = 0; kk4 < 16; kk4++) {
            ulonglong2 v0 = *(ulonglong2*)&Vs[(4 * kk4 + 0) * 68 + tx * 4];
            ulonglong2 v1 = *(ulonglong2*)&Vs[(4 * kk4 + 1) * 68 + tx * 4];
            ulonglong2 v2 = *(ulonglong2*)&Vs[(4 * kk4 + 2) * 68 + tx * 4];
            ulonglong2 v3 = *(ulonglong2*)&Vs[(4 * kk4 + 3) * 68 + tx * 4];
#pragma unroll
            for (int i = 0; i < 8; i++) {
                float4 pf = *(float4*)&KPs[(ty * 8 + i) * 68 + 4 * kk4];
                unsigned long long p0 = pack2(pf.x, pf.x);
                unsigned long long p1 = pack2(pf.y, pf.y);
                unsigned long long p2 = pack2(pf.z, pf.z);
                unsigned long long p3 = pack2(pf.w, pf.w);
                fma2(o2[i][0], p0, v0.x); fma2(o2[i][1], p0, v0.y);
                fma2(o2[i][0], p1, v1.x); fma2(o2[i][1], p1, v1.y);
                fma2(o2[i][0], p2, v2.x); fma2(o2[i][1], p2, v2.y);
                fma2(o2[i][0], p3, v3.x); fma2(o2[i][1], p3, v3.y);
            }
        }
    }

    __syncthreads();
    float* Os = KPs;   // [64][65]
#pragma unroll
    for (int i = 0; i < 8; i++) {
        float inv = 1.f / l_i[i];
        float a, bv, c, d;
        unpack2(o2[i][0], a, bv);
        unpack2(o2[i][1], c, d);
        int q = ty * 8 + i;
        Os[q * 65 + tx * 4 + 0] = a * inv;
        Os[q * 65 + tx * 4 + 1] = bv * inv;
        Os[q * 65 + tx * 4 + 2] = c * inv;
        Os[q * 65 + tx * 4 + 3] = d * inv;
    }
    __syncthreads();
#pragma unroll
    for (int r = 0; r < 32; r++) {
        int idx = tid + r * 128;
        int dd = idx >> 6, nl = idx & 63;
        out[((size_t)(b * C_ + p * 64 + dd)) * N_ + n0 + nl] = Os[nl * 65 + dd];
    }
}

// ---------------- launch ----------------
extern "C" void kernel_launch(void* const* d_in, const int* in_sizes, int n_in,
                              void* d_out, int out_size) {
    const float* x     = (const float*)d_in[0];
    const float* qkv_w = (const float*)d_in[1];
    const float* h_pos = (const float*)d_in[2];
    const float* w_pos = (const float*)d_in[3];
    float* out = (float*)d_out;

    rpT_kernel<<<(P_ * D_ * N_ + 255) / 256, 256>>>(h_pos, w_pos);

    dim3 gs(32, 16, B_);   // n-tiles, c-tiles, batch
    split_x_kernel<<<gs, 256>>>(x);
    split_w_kernel<<<(3 * C_ * C_ / 4 + 255) / 256, 256>>>(qkv_w);

    cudaFuncSetAttribute(qkv_mma_kernel,
                         cudaFuncAttributeMaxDynamicSharedMemorySize, QKV_SMEM);
    dim3 g1(12, 8, B_);    // o-blocks, n-tiles, batch
    qkv_mma_kernel<<<g1, 256, QKV_SMEM>>>();

    const int attn_smem = 3 * SM_T * (int)sizeof(float);  // 52224
    cudaFuncSetAttribute(attn_kernel,
                         cudaFuncAttributeMaxDynamicSharedMemorySize, attn_smem);
    dim3 g2(16, P_, B_);
    attn_kernel<<<g2, 128, attn_smem>>>(out);
}

// round 11
// speedup vs baseline: 5.3289x; 1.5737x over previous
#include <cuda_runtime.h>
#include <cuda_bf16.h>
#include <math.h>
#include <cstdint>

#define B_ 32
#define C_ 512
#define P_ 8
#define D_ 64
#define N_ 1024   // 32*32

// ---------------- scratch (__device__ globals: alloc-free rule) ----------------
__device__ __nv_bfloat16 g_qh[(size_t)B_ * P_ * N_ * D_];  // [b,p,n,d]
__device__ __nv_bfloat16 g_ql[(size_t)B_ * P_ * N_ * D_];
__device__ __nv_bfloat16 g_kh[(size_t)B_ * P_ * N_ * D_];  // [b,p,n,d] (k+rp)
__device__ __nv_bfloat16 g_kl[(size_t)B_ * P_ * N_ * D_];
__device__ __nv_bfloat16 g_vh[(size_t)B_ * P_ * D_ * N_];  // [b,p,d,n]
__device__ __nv_bfloat16 g_vl[(size_t)B_ * P_ * D_ * N_];
__device__ float g_rp[(size_t)P_ * N_ * D_];               // [p,n,d]
__device__ __nv_bfloat16 g_xh[(size_t)B_ * N_ * C_];       // x^T hi [b,n,c]
__device__ __nv_bfloat16 g_xl[(size_t)B_ * N_ * C_];
__device__ __nv_bfloat16 g_wh[(size_t)3 * C_ * C_];        // w hi [o,c]
__device__ __nv_bfloat16 g_wl[(size_t)3 * C_ * C_];

// ---------------- warp-MMA helpers (baseline ISA: sm_80+) ----------------
__device__ __forceinline__ uint32_t smem_u32(const void* p) {
    uint32_t a;
    asm("{ .reg .u64 t; cvta.to.shared.u64 t, %1; cvt.u32.u64 %0, t; }" : "=r"(a) : "l"(p));
    return a;
}
__device__ __forceinline__ void ldsm4(uint32_t a, uint32_t r[4]) {
    asm volatile("ldmatrix.sync.aligned.m8n8.x4.shared.b16 {%0,%1,%2,%3}, [%4];"
        : "=r"(r[0]), "=r"(r[1]), "=r"(r[2]), "=r"(r[3]) : "r"(a));
}
__device__ __forceinline__ void ldsm2(uint32_t a, uint32_t r[2]) {
    asm volatile("ldmatrix.sync.aligned.m8n8.x2.shared.b16 {%0,%1}, [%2];"
        : "=r"(r[0]), "=r"(r[1]) : "r"(a));
}
__device__ __forceinline__ void mma16816(float c[4], const uint32_t a[4], const uint32_t b[2]) {
    asm volatile("mma.sync.aligned.m16n8k16.row.col.f32.bf16.bf16.f32 "
        "{%0,%1,%2,%3}, {%4,%5,%6,%7}, {%8,%9}, {%0,%1,%2,%3};"
        : "+f"(c[0]), "+f"(c[1]), "+f"(c[2]), "+f"(c[3])
        : "r"(a[0]), "r"(a[1]), "r"(a[2]), "r"(a[3]), "r"(b[0]), "r"(b[1]));
}
__device__ __forceinline__ void cpa16(uint32_t s, const void* g) {
    asm volatile("cp.async.cg.shared.global [%0], [%1], 16;" :: "r"(s), "l"(g));
}
#define CP_COMMIT()  asm volatile("cp.async.commit_group;" ::: "memory")
#define CP_WAIT(n)   asm volatile("cp.async.wait_group %0;" :: "n"(n) : "memory")

__device__ __forceinline__ void split_bf(float f, unsigned short& h, unsigned short& l) {
    __nv_bfloat16 hb = __float2bfloat16(f);
    h = __bfloat16_as_ushort(hb);
    l = __bfloat16_as_ushort(__float2bfloat16(f - __bfloat162float(hb)));
}
__device__ __forceinline__ uint32_t packus(unsigned short lo, unsigned short hi) {
    return (uint32_t)lo | ((uint32_t)hi << 16);
}

// ---------------- kernel 0: relative position table [p,n,d] ----------------
__global__ void rp_kernel(const float* __restrict__ h_pos,
                          const float* __restrict__ w_pos) {
    int idx = blockIdx.x * blockDim.x + threadIdx.x;
    if (idx >= P_ * N_ * D_) return;
    int dd = idx & 63;
    int n  = (idx >> 6) & (N_ - 1);
    int p  = idx >> 16;
    int c  = p * 64 + dd;
    g_rp[idx] = h_pos[(n >> 5) * C_ + c] + w_pos[(n & 31) * C_ + c];
}

// ---------------- kernel 0b: split+transpose X -> bf16 hi/lo [b,n,c] ----------------
__global__ __launch_bounds__(256)
void split_x_kernel(const float* __restrict__ x) {
    __shared__ float ts[32][33];
    const int b  = blockIdx.z;
    const int c0 = blockIdx.y * 32;
    const int n0 = blockIdx.x * 32;
    const int t = threadIdx.x;
    const int r = t >> 3, q4 = (t & 7) * 4;
    float4 v = *(const float4*)&x[((size_t)b * C_ + c0 + r) * N_ + n0 + q4];
    ts[r][q4] = v.x; ts[r][q4 + 1] = v.y; ts[r][q4 + 2] = v.z; ts[r][q4 + 3] = v.w;
    __syncthreads();
    ushort4 hi, lo;
    float f[4];
#pragma unroll
    for (int i = 0; i < 4; i++) f[i] = ts[q4 + i][r];
    split_bf(f[0], hi.x, lo.x); split_bf(f[1], hi.y, lo.y);
    split_bf(f[2], hi.z, lo.z); split_bf(f[3], hi.w, lo.w);
    size_t o = ((size_t)b * N_ + n0 + r) * C_ + c0 + q4;
    *(ushort4*)&g_xh[o] = hi;
    *(ushort4*)&g_xl[o] = lo;
}

// ---------------- kernel 0c: split W -> bf16 hi/lo [o,c] ----------------
__global__ void split_w_kernel(const float* __restrict__ w) {
    int f4 = blockIdx.x * blockDim.x + threadIdx.x;
    if (f4 >= 3 * C_ * C_ / 4) return;
    float4 v = ((const float4*)w)[f4];
    ushort4 hi, lo;
    split_bf(v.x, hi.x, lo.x); split_bf(v.y, hi.y, lo.y);
    split_bf(v.z, hi.z, lo.z); split_bf(v.w, hi.w, lo.w);
    ((ushort4*)g_wh)[f4] = hi;
    ((ushort4*)g_wl)[f4] = lo;
}

// ---------------- kernel 1: QKV GEMM via mma.sync bf16 split (3-term) ----------------
// q/k blocks (ob 0..7): A=X (rows n), B=W -> D[n][o] -> write [b,p,n,d] bf16 hi/lo (+rp for k)
// v  blocks (ob 8..11): A=W (rows o), B=X -> D[o][n] -> write [b,p,d,n] bf16 hi/lo
#define TILE_B 18432u           // 128 rows * 144 B
#define BUF_B  (4u * TILE_B)
#define QKV_SMEM (2 * 4 * 18432)

__global__ __launch_bounds__(256)
void qkv_mma_kernel() {
    extern __shared__ char dynsm[];
    const int b  = blockIdx.z;
    const int nt = blockIdx.y;
    const int ob = blockIdx.x;
    const int o0 = ob * 128;
    const int tid = threadIdx.x;
    const int lane = tid & 31, wid = tid >> 5;
    const int wm = wid & 3, wn = wid >> 2;   // 4 (M) x 2 (N) warps

    const uint32_t sb = smem_u32(dynsm);
    const bool aIsX = (ob < 8);              // q/k: A = X

    const __nv_bfloat16* wh = g_wh + (size_t)o0 * C_;
    const __nv_bfloat16* wl = g_wl + (size_t)o0 * C_;
    const __nv_bfloat16* xh = g_xh + ((size_t)b * N_ + nt * 128) * C_;
    const __nv_bfloat16* xl = g_xl + ((size_t)b * N_ + nt * 128) * C_;

    auto issue = [&](int ch) {
        const int kc0 = ch * 64;
        const uint32_t buf = sb + (uint32_t)(ch & 1) * BUF_B;
#pragma unroll
        for (int j = 0; j < 4; j++) {
            int flat = tid + j * 256;
            int row = flat >> 3, c8 = flat & 7;
            uint32_t so = (uint32_t)(row * 144 + c8 * 16);
            size_t go = (size_t)row * C_ + kc0 + c8 * 8;
            cpa16(buf + 0 * TILE_B + so, wh + go);
            cpa16(buf + 1 * TILE_B + so, wl + go);
            cpa16(buf + 2 * TILE_B + so, xh + go);
            cpa16(buf + 3 * TILE_B + so, xl + go);
        }
    };

    float acc[2][8][4];
#pragma unroll
    for (int ma = 0; ma < 2; ma++)
#pragma unroll
        for (int na = 0; na < 8; na++)
#pragma unroll
            for (int q = 0; q < 4; q++) acc[ma][na][q] = 0.f;

    issue(0); CP_COMMIT();
    for (int ch = 0; ch < 8; ch++) {
        if (ch < 7) { issue(ch + 1); CP_COMMIT(); CP_WAIT(1); }
        else        { CP_WAIT(0); }
        __syncthreads();
        const uint32_t buf = sb + (uint32_t)(ch & 1) * BUF_B;
        const uint32_t Ah = buf + (aIsX ? 2 * TILE_B : 0);
        const uint32_t Al = Ah + TILE_B;
        const uint32_t Bh = buf + (aIsX ? 0 : 2 * TILE_B);
        const uint32_t Bl = Bh + TILE_B;
#pragma unroll
        for (int ks = 0; ks < 4; ks++) {
            const int k0 = ks * 16;
            uint32_t ah[2][4], al[2][4];
#pragma unroll
            for (int ma = 0; ma < 2; ma++) {
                uint32_t aoff = (uint32_t)((wm * 32 + ma * 16 + (lane & 15)) * 144 +
                                           k0 * 2 + (lane >> 4) * 16);
                ldsm4(Ah + aoff, ah[ma]);
                ldsm4(Al + aoff, al[ma]);
            }
#pragma unroll
            for (int na = 0; na < 8; na++) {
                uint32_t boff = (uint32_t)((wn * 64 + na * 8 + (lane & 7)) * 144 +
                                           k0 * 2 + ((lane >> 3) & 1) * 16);
                uint32_t bh[2], bl[2];
                ldsm2(Bh + boff, bh);
                ldsm2(Bl + boff, bl);
#pragma unroll
                for (int ma = 0; ma < 2; ma++) {
                    mma16816(acc[ma][na], ah[ma], bh);
                    mma16816(acc[ma][na], ah[ma], bl);
                    mma16816(acc[ma][na], al[ma], bh);
                }
            }
        }
        __syncthreads();
    }

    // ---- epilogue: split to bf16 hi/lo ----
    const int which = o0 >> 9;                 // 0=q 1=k 2=v
    if (aIsX) {
        __nv_bfloat16* dh = which ? g_kh : g_qh;
        __nv_bfloat16* dl = which ? g_kl : g_ql;
#pragma unroll
        for (int ma = 0; ma < 2; ma++) {
#pragma unroll
            for (int half = 0; half < 2; half++) {
                int nrow = nt * 128 + wm * 32 + ma * 16 + (lane >> 2) + half * 8;
#pragma unroll
                for (int na = 0; na < 8; na++) {
                    int oc = (o0 & 511) + wn * 64 + na * 8 + (lane & 3) * 2;
                    int p = oc >> 6, d = oc & 63;
                    float c0 = acc[ma][na][half * 2], c1 = acc[ma][na][half * 2 + 1];
                    if (which == 1) {
                        float2 r = *(const float2*)&g_rp[((size_t)p * N_ + nrow) * D_ + d];
                        c0 += r.x; c1 += r.y;
                    }
                    unsigned short h0, l0, h1, l1;
                    split_bf(c0, h0, l0); split_bf(c1, h1, l1);
                    size_t off = ((size_t)(b * P_ + p) * N_ + nrow) * D_ + d;
                    *(uint32_t*)&dh[off] = packus(h0, h1);
                    *(uint32_t*)&dl[off] = packus(l0, l1);
                }
            }
        }
    } else {
#pragma unroll
        for (int ma = 0; ma < 2; ma++) {
#pragma unroll
            for (int half = 0; half < 2; half++) {
                int oc = (o0 & 511) + wm * 32 + ma * 16 + (lane >> 2) + half * 8;
                int p = oc >> 6, d = oc & 63;
#pragma unroll
                for (int na = 0; na < 8; na++) {
                    int n = nt * 128 + wn * 64 + na * 8 + (lane & 3) * 2;
                    unsigned short h0, l0, h1, l1;
                    split_bf(acc[ma][na][half * 2], h0, l0);
                    split_bf(acc[ma][na][half * 2 + 1], h1, l1);
                    size_t off = ((size_t)(b * P_ + p) * D_ + d) * N_ + n;
                    *(uint32_t*)&g_vh[off] = packus(h0, h1);
                    *(uint32_t*)&g_vl[off] = packus(l0, l1);
                }
            }
        }
    }
}

// ---------------- kernel 2: flash attention via mma.sync bf16 split ----------------
// 128 threads = 4 warps; Br=64 (warp owns 16 q-rows), Bc=64.
// smem: Qh|Ql (9216 ea) + 2 x {Kh,Kl,Vh,Vl} (9216 ea) = 92160 B
#define ATT_SMEM (18432 + 2 * 36864)

__global__ __launch_bounds__(128)
void attn_mma_kernel(float* __restrict__ out) {
    extern __shared__ char dynsm[];
    const int b  = blockIdx.z;
    const int p  = blockIdx.y;
    const int n0 = blockIdx.x * 64;
    const int tid = threadIdx.x;
    const int lane = tid & 31, wm = tid >> 5;

    const uint32_t base = smem_u32(dynsm);
    const size_t hb  = (size_t)(b * P_ + p) * N_ * D_;
    const size_t hbV = (size_t)(b * P_ + p) * D_ * N_;

    // Q tiles (once)
#pragma unroll
    for (int it = 0; it < 4; it++) {
        int idx = tid + it * 128;
        int row = idx >> 3, c8 = idx & 7;
        size_t g = hb + (size_t)(n0 + row) * D_ + c8 * 8;
        *(uint4*)(dynsm + row * 144 + c8 * 16)        = *(const uint4*)&g_qh[g];
        *(uint4*)(dynsm + 9216 + row * 144 + c8 * 16) = *(const uint4*)&g_ql[g];
    }

    auto issueKV = [&](int kt) {
        uint32_t buf = base + 18432 + (uint32_t)(kt & 1) * 36864;
#pragma unroll
        for (int it = 0; it < 4; it++) {
            int idx = tid + it * 128;
            int row = idx >> 3, c8 = idx & 7;
            uint32_t so = (uint32_t)(row * 144 + c8 * 16);
            size_t gk = hb + (size_t)(kt * 64 + row) * D_ + c8 * 8;
            size_t gv = hbV + (size_t)row * N_ + kt * 64 + c8 * 8;
            cpa16(buf + 0 * 9216 + so, g_kh + gk);
            cpa16(buf + 1 * 9216 + so, g_kl + gk);
            cpa16(buf + 2 * 9216 + so, g_vh + gv);
            cpa16(buf + 3 * 9216 + so, g_vl + gv);
        }
    };

    float m_i[2] = {-INFINITY, -INFINITY};
    float l_i[2] = {0.f, 0.f};
    float o_acc[8][4];
#pragma unroll
    for (int f = 0; f < 8; f++)
#pragma unroll
        for (int q = 0; q < 4; q++) o_acc[f][q] = 0.f;

    issueKV(0); CP_COMMIT();

    for (int kt = 0; kt < 16; kt++) {
        if (kt < 15) { issueKV(kt + 1); CP_COMMIT(); CP_WAIT(1); }
        else         { CP_WAIT(0); }
        __syncthreads();
        const uint32_t buf = base + 18432 + (uint32_t)(kt & 1) * 36864;
        const uint32_t Kh = buf, Kl = buf + 9216, Vh = buf + 18432, Vl = buf + 27648;

        // S = Q K^T (3-term split)
        float sc[8][4];
#pragma unroll
        for (int f = 0; f < 8; f++)
#pragma unroll
            for (int q = 0; q < 4; q++) sc[f][q] = 0.f;

#pragma unroll
        for (int ks = 0; ks < 4; ks++) {
            uint32_t aoff = (uint32_t)((wm * 16 + (lane & 15)) * 144 +
                                       ks * 32 + (lane >> 4) * 16);
            uint32_t qh[4], ql[4];
            ldsm4(base + aoff, qh);
            ldsm4(base + 9216 + aoff, ql);
#pragma unroll
            for (int f = 0; f < 8; f++) {
                uint32_t boff = (uint32_t)((f * 8 + (lane & 7)) * 144 +
                                           ks * 32 + ((lane >> 3) & 1) * 16);
                uint32_t kh[2], kl[2];
                ldsm2(Kh + boff, kh);
                ldsm2(Kl + boff, kl);
                mma16816(sc[f], qh, kh);
                mma16816(sc[f], qh, kl);
                mma16816(sc[f], ql, kh);
            }
        }

        // online softmax: thread rows r0=lane>>2, r1=r0+8
        float rm0 = -INFINITY, rm1 = -INFINITY;
#pragma unroll
        for (int f = 0; f < 8; f++) {
            rm0 = fmaxf(rm0, fmaxf(sc[f][0], sc[f][1]));
            rm1 = fmaxf(rm1, fmaxf(sc[f][2], sc[f][3]));
        }
        rm0 = fmaxf(rm0, __shfl_xor_sync(0xffffffffu, rm0, 1));
        rm0 = fmaxf(rm0, __shfl_xor_sync(0xffffffffu, rm0, 2));
        rm1 = fmaxf(rm1, __shfl_xor_sync(0xffffffffu, rm1, 1));
        rm1 = fmaxf(rm1, __shfl_xor_sync(0xffffffffu, rm1, 2));
        float mn0 = fmaxf(m_i[0], rm0), mn1 = fmaxf(m_i[1], rm1);
        float corr0 = __expf(m_i[0] - mn0), corr1 = __expf(m_i[1] - mn1);
        float rs0 = 0.f, rs1 = 0.f;
#pragma unroll
        for (int f = 0; f < 8; f++) {
            sc[f][0] = __expf(sc[f][0] - mn0);
            sc[f][1] = __expf(sc[f][1] - mn0);
            sc[f][2] = __expf(sc[f][2] - mn1);
            sc[f][3] = __expf(sc[f][3] - mn1);
            rs0 += sc[f][0] + sc[f][1];
            rs1 += sc[f][2] + sc[f][3];
        }
        rs0 += __shfl_xor_sync(0xffffffffu, rs0, 1);
        rs0 += __shfl_xor_sync(0xffffffffu, rs0, 2);
        rs1 += __shfl_xor_sync(0xffffffffu, rs1, 1);
        rs1 += __shfl_xor_sync(0xffffffffu, rs1, 2);
        l_i[0] = l_i[0] * corr0 + rs0;
        l_i[1] = l_i[1] * corr1 + rs1;
        m_i[0] = mn0; m_i[1] = mn1;
#pragma unroll
        for (int f = 0; f < 8; f++) {
            o_acc[f][0] *= corr0; o_acc[f][1] *= corr0;
            o_acc[f][2] *= corr1; o_acc[f][3] *= corr1;
        }

        // O += P V (P split in registers; V split in smem, [d][key] layout)
#pragma unroll
        for (int kc = 0; kc < 4; kc++) {
            const int f0 = 2 * kc, f1 = 2 * kc + 1;
            uint32_t ah[4], al[4];
            unsigned short h[8], l[8];
            split_bf(sc[f0][0], h[0], l[0]); split_bf(sc[f0][1], h[1], l[1]);
            split_bf(sc[f0][2], h[2], l[2]); split_bf(sc[f0][3], h[3], l[3]);
            split_bf(sc[f1][0], h[4], l[4]); split_bf(sc[f1][1], h[5], l[5]);
            split_bf(sc[f1][2], h[6], l[6]); split_bf(sc[f1][3], h[7], l[7]);
            ah[0] = packus(h[0], h[1]); ah[1] = packus(h[2], h[3]);
            ah[2] = packus(h[4], h[5]); ah[3] = packus(h[6], h[7]);
            al[0] = packus(l[0], l[1]); al[1] = packus(l[2], l[3]);
            al[2] = packus(l[4], l[5]); al[3] = packus(l[6], l[7]);
#pragma unroll
            for (int df = 0; df < 8; df++) {
                uint32_t boff = (uint32_t)((df * 8 + (lane & 7)) * 144 +
                                           kc * 32 + ((lane >> 3) & 1) * 16);
                uint32_t vh[2], vl[2];
                ldsm2(Vh + boff, vh);
                ldsm2(Vl + boff, vl);
                mma16816(o_acc[df], ah, vh);
                mma16816(o_acc[df], ah, vl);
                mma16816(o_acc[df], al, vh);
            }
        }
        __syncthreads();
    }

    // epilogue: normalize, stage [d][q] in smem, coalesced store out[b, p*64+d, n]
    float inv0 = 1.f / l_i[0], inv1 = 1.f / l_i[1];
    float* Os = (float*)(dynsm + 18432);   // [64][68]
#pragma unroll
    for (int df = 0; df < 8; df++) {
        int d0 = df * 8 + 2 * (lane & 3);
        int q0 = wm * 16 + (lane >> 2);
        Os[(d0 + 0) * 68 + q0]     = o_acc[df][0] * inv0;
        Os[(d0 + 1) * 68 + q0]     = o_acc[df][1] * inv0;
        Os[(d0 + 0) * 68 + q0 + 8] = o_acc[df][2] * inv1;
        Os[(d0 + 1) * 68 + q0 + 8] = o_acc[df][3] * inv1;
    }
    __syncthreads();
#pragma unroll
    for (int it = 0; it < 8; it++) {
        int idx = tid + it * 128;          // 0..1023 float4s
        int d = idx >> 4, q4 = (idx & 15) * 4;
        float4 v = *(float4*)&Os[d * 68 + q4];
        *(float4*)&out[((size_t)(b * C_ + p * 64 + d)) * N_ + n0 + q4] = v;
    }
}

// ---------------- launch ----------------
extern "C" void kernel_launch(void* const* d_in, const int* in_sizes, int n_in,
                              void* d_out, int out_size) {
    const float* x     = (const float*)d_in[0];
    const float* qkv_w = (const float*)d_in[1];
    const float* h_pos = (const float*)d_in[2];
    const float* w_pos = (const float*)d_in[3];
    float* out = (float*)d_out;

    rp_kernel<<<(P_ * N_ * D_ + 255) / 256, 256>>>(h_pos, w_pos);

    dim3 gs(32, 16, B_);   // n-tiles, c-tiles, batch
    split_x_kernel<<<gs, 256>>>(x);
    split_w_kernel<<<(3 * C_ * C_ / 4 + 255) / 256, 256>>>(qkv_w);

    cudaFuncSetAttribute(qkv_mma_kernel,
                         cudaFuncAttributeMaxDynamicSharedMemorySize, QKV_SMEM);
    dim3 g1(12, 8, B_);    // o-blocks, n-tiles, batch
    qkv_mma_kernel<<<g1, 256, QKV_SMEM>>>();

    cudaFuncSetAttribute(attn_mma_kernel,
                         cudaFuncAttributeMaxDynamicSharedMemorySize, ATT_SMEM);
    dim3 g2(16, P_, B_);   // q-tiles, heads, batch
    attn_mma_kernel<<<g2, 128, ATT_SMEM>>>(out);
}

// round 12
// speedup vs baseline: 6.3170x; 1.1854x over previous
#include <cuda_runtime.h>
#include <cuda_bf16.h>
#include <math.h>
#include <cstdint>

#define B_ 32
#define C_ 512
#define P_ 8
#define D_ 64
#define N_ 1024   // 32*32

// ---------------- scratch (__device__ globals: alloc-free rule) ----------------
__device__ __nv_bfloat16 g_qh[(size_t)B_ * P_ * N_ * D_];  // [b,p,n,d]
__device__ __nv_bfloat16 g_ql[(size_t)B_ * P_ * N_ * D_];
__device__ __nv_bfloat16 g_kh[(size_t)B_ * P_ * N_ * D_];  // [b,p,n,d] (k+rp)
__device__ __nv_bfloat16 g_kl[(size_t)B_ * P_ * N_ * D_];
__device__ __nv_bfloat16 g_vh[(size_t)B_ * P_ * D_ * N_];  // [b,p,d,n]
__device__ __nv_bfloat16 g_vl[(size_t)B_ * P_ * D_ * N_];
__device__ float g_rp[(size_t)P_ * N_ * D_];               // [p,n,d]
__device__ __nv_bfloat16 g_xh[(size_t)B_ * N_ * C_];       // x^T hi [b,n,c]
__device__ __nv_bfloat16 g_xl[(size_t)B_ * N_ * C_];
__device__ __nv_bfloat16 g_wh[(size_t)3 * C_ * C_];        // w hi [o,c]
__device__ __nv_bfloat16 g_wl[(size_t)3 * C_ * C_];

// ---------------- warp-MMA helpers (baseline ISA: sm_80+) ----------------
__device__ __forceinline__ uint32_t smem_u32(const void* p) {
    uint32_t a;
    asm("{ .reg .u64 t; cvta.to.shared.u64 t, %1; cvt.u32.u64 %0, t; }" : "=r"(a) : "l"(p));
    return a;
}
__device__ __forceinline__ void ldsm4(uint32_t a, uint32_t r[4]) {
    asm volatile("ldmatrix.sync.aligned.m8n8.x4.shared.b16 {%0,%1,%2,%3}, [%4];"
        : "=r"(r[0]), "=r"(r[1]), "=r"(r[2]), "=r"(r[3]) : "r"(a));
}
__device__ __forceinline__ void ldsm2(uint32_t a, uint32_t r[2]) {
    asm volatile("ldmatrix.sync.aligned.m8n8.x2.shared.b16 {%0,%1}, [%2];"
        : "=r"(r[0]), "=r"(r[1]) : "r"(a));
}
__device__ __forceinline__ void mma16816(float c[4], const uint32_t a[4], const uint32_t b[2]) {
    asm volatile("mma.sync.aligned.m16n8k16.row.col.f32.bf16.bf16.f32 "
        "{%0,%1,%2,%3}, {%4,%5,%6,%7}, {%8,%9}, {%0,%1,%2,%3};"
        : "+f"(c[0]), "+f"(c[1]), "+f"(c[2]), "+f"(c[3])
        : "r"(a[0]), "r"(a[1]), "r"(a[2]), "r"(a[3]), "r"(b[0]), "r"(b[1]));
}
__device__ __forceinline__ void cpa16(uint32_t s, const void* g) {
    asm volatile("cp.async.cg.shared.global [%0], [%1], 16;" :: "r"(s), "l"(g));
}
#define CP_COMMIT()  asm volatile("cp.async.commit_group;" ::: "memory")
#define CP_WAIT(n)   asm volatile("cp.async.wait_group %0;" :: "n"(n) : "memory")

__device__ __forceinline__ void split_bf(float f, unsigned short& h, unsigned short& l) {
    __nv_bfloat16 hb = __float2bfloat16(f);
    h = __bfloat16_as_ushort(hb);
    l = __bfloat16_as_ushort(__float2bfloat16(f - __bfloat162float(hb)));
}
__device__ __forceinline__ uint32_t packus(unsigned short lo, unsigned short hi) {
    return (uint32_t)lo | ((uint32_t)hi << 16);
}

// ---------------- kernel 0: relative position table [p,n,d] ----------------
__global__ void rp_kernel(const float* __restrict__ h_pos,
                          const float* __restrict__ w_pos) {
    int idx = blockIdx.x * blockDim.x + threadIdx.x;
    if (idx >= P_ * N_ * D_) return;
    int dd = idx & 63;
    int n  = (idx >> 6) & (N_ - 1);
    int p  = idx >> 16;
    int c  = p * 64 + dd;
    g_rp[idx] = h_pos[(n >> 5) * C_ + c] + w_pos[(n & 31) * C_ + c];
}

// ---------------- kernel 0b: split+transpose X -> bf16 hi/lo [b,n,c] ----------------
__global__ __launch_bounds__(256)
void split_x_kernel(const float* __restrict__ x) {
    __shared__ float ts[32][33];
    const int b  = blockIdx.z;
    const int c0 = blockIdx.y * 32;
    const int n0 = blockIdx.x * 32;
    const int t = threadIdx.x;
    const int r = t >> 3, q4 = (t & 7) * 4;
    float4 v = *(const float4*)&x[((size_t)b * C_ + c0 + r) * N_ + n0 + q4];
    ts[r][q4] = v.x; ts[r][q4 + 1] = v.y; ts[r][q4 + 2] = v.z; ts[r][q4 + 3] = v.w;
    __syncthreads();
    ushort4 hi, lo;
    float f[4];
#pragma unroll
    for (int i = 0; i < 4; i++) f[i] = ts[q4 + i][r];
    split_bf(f[0], hi.x, lo.x); split_bf(f[1], hi.y, lo.y);
    split_bf(f[2], hi.z, lo.z); split_bf(f[3], hi.w, lo.w);
    size_t o = ((size_t)b * N_ + n0 + r) * C_ + c0 + q4;
    *(ushort4*)&g_xh[o] = hi;
    *(ushort4*)&g_xl[o] = lo;
}

// ---------------- kernel 0c: split W -> bf16 hi/lo [o,c] ----------------
__global__ void split_w_kernel(const float* __restrict__ w) {
    int f4 = blockIdx.x * blockDim.x + threadIdx.x;
    if (f4 >= 3 * C_ * C_ / 4) return;
    float4 v = ((const float4*)w)[f4];
    ushort4 hi, lo;
    split_bf(v.x, hi.x, lo.x); split_bf(v.y, hi.y, lo.y);
    split_bf(v.z, hi.z, lo.z); split_bf(v.w, hi.w, lo.w);
    ((ushort4*)g_wh)[f4] = hi;
    ((ushort4*)g_wl)[f4] = lo;
}

// ---------------- kernel 1: QKV GEMM via mma.sync bf16 split, BK=32 (2 CTAs/SM) ----------------
// q/k blocks (ob 0..7): A=X (rows n), B=W -> D[n][o] -> [b,p,n,d] bf16 hi/lo (+rp for k)
// v  blocks (ob 8..11): A=W (rows o), B=X -> D[o][n] -> [b,p,d,n] bf16 hi/lo
#define TILE_B 10240u           // 128 rows * 80 B (32 bf16 + 8 pad)
#define BUF_B  (4u * TILE_B)    // Wh | Wl | Xh | Xl
#define QKV_SMEM (2 * 4 * 10240)

__global__ __launch_bounds__(256, 2)
void qkv_mma_kernel() {
    extern __shared__ char dynsm[];
    const int b  = blockIdx.z;
    const int nt = blockIdx.y;
    const int ob = blockIdx.x;
    const int o0 = ob * 128;
    const int tid = threadIdx.x;
    const int lane = tid & 31, wid = tid >> 5;
    const int wm = wid & 3, wn = wid >> 2;   // 4 (M) x 2 (N) warps

    const uint32_t sb = smem_u32(dynsm);
    const bool aIsX = (ob < 8);              // q/k: A = X

    const __nv_bfloat16* wh = g_wh + (size_t)o0 * C_;
    const __nv_bfloat16* wl = g_wl + (size_t)o0 * C_;
    const __nv_bfloat16* xh = g_xh + ((size_t)b * N_ + nt * 128) * C_;
    const __nv_bfloat16* xl = g_xl + ((size_t)b * N_ + nt * 128) * C_;

    auto issue = [&](int ch) {
        const int kc0 = ch * 32;
        const uint32_t buf = sb + (uint32_t)(ch & 1) * BUF_B;
#pragma unroll
        for (int j = 0; j < 2; j++) {
            int flat = tid + j * 256;          // 0..511
            int row = flat >> 2, c4 = flat & 3;
            uint32_t so = (uint32_t)(row * 80 + c4 * 16);
            size_t go = (size_t)row * C_ + kc0 + c4 * 8;
            cpa16(buf + 0 * TILE_B + so, wh + go);
            cpa16(buf + 1 * TILE_B + so, wl + go);
            cpa16(buf + 2 * TILE_B + so, xh + go);
            cpa16(buf + 3 * TILE_B + so, xl + go);
        }
    };

    float acc[2][8][4];
#pragma unroll
    for (int ma = 0; ma < 2; ma++)
#pragma unroll
        for (int na = 0; na < 8; na++)
#pragma unroll
            for (int q = 0; q < 4; q++) acc[ma][na][q] = 0.f;

    issue(0); CP_COMMIT();
    for (int ch = 0; ch < 16; ch++) {
        if (ch < 15) { issue(ch + 1); CP_COMMIT(); CP_WAIT(1); }
        else         { CP_WAIT(0); }
        __syncthreads();
        const uint32_t buf = sb + (uint32_t)(ch & 1) * BUF_B;
        const uint32_t Ah = buf + (aIsX ? 2 * TILE_B : 0);
        const uint32_t Al = Ah + TILE_B;
        const uint32_t Bh = buf + (aIsX ? 0 : 2 * TILE_B);
        const uint32_t Bl = Bh + TILE_B;
#pragma unroll
        for (int ks = 0; ks < 2; ks++) {
            uint32_t ah[2][4], al[2][4];
#pragma unroll
            for (int ma = 0; ma < 2; ma++) {
                uint32_t aoff = (uint32_t)((wm * 32 + ma * 16 + (lane & 15)) * 80 +
                                           ks * 32 + (lane >> 4) * 16);
                ldsm4(Ah + aoff, ah[ma]);
                ldsm4(Al + aoff, al[ma]);
            }
#pragma unroll
            for (int na = 0; na < 8; na++) {
                uint32_t boff = (uint32_t)((wn * 64 + na * 8 + (lane & 7)) * 80 +
                                           ks * 32 + ((lane >> 3) & 1) * 16);
                uint32_t bh[2], bl[2];
                ldsm2(Bh + boff, bh);
                ldsm2(Bl + boff, bl);
#pragma unroll
                for (int ma = 0; ma < 2; ma++) {
                    mma16816(acc[ma][na], ah[ma], bh);
                    mma16816(acc[ma][na], ah[ma], bl);
                    mma16816(acc[ma][na], al[ma], bh);
                }
            }
        }
        __syncthreads();
    }

    // ---- epilogue: split to bf16 hi/lo ----
    const int which = o0 >> 9;                 // 0=q 1=k 2=v
    if (aIsX) {
        __nv_bfloat16* dh = which ? g_kh : g_qh;
        __nv_bfloat16* dl = which ? g_kl : g_ql;
#pragma unroll
        for (int ma = 0; ma < 2; ma++) {
#pragma unroll
            for (int half = 0; half < 2; half++) {
                int nrow = nt * 128 + wm * 32 + ma * 16 + (lane >> 2) + half * 8;
#pragma unroll
                for (int na = 0; na < 8; na++) {
                    int oc = (o0 & 511) + wn * 64 + na * 8 + (lane & 3) * 2;
                    int p = oc >> 6, d = oc & 63;
                    float c0 = acc[ma][na][half * 2], c1 = acc[ma][na][half * 2 + 1];
                    if (which == 1) {
                        float2 r = *(const float2*)&g_rp[((size_t)p * N_ + nrow) * D_ + d];
                        c0 += r.x; c1 += r.y;
                    }
                    unsigned short h0, l0, h1, l1;
                    split_bf(c0, h0, l0); split_bf(c1, h1, l1);
                    size_t off = ((size_t)(b * P_ + p) * N_ + nrow) * D_ + d;
                    *(uint32_t*)&dh[off] = packus(h0, h1);
                    *(uint32_t*)&dl[off] = packus(l0, l1);
                }
            }
        }
    } else {
#pragma unroll
        for (int ma = 0; ma < 2; ma++) {
#pragma unroll
            for (int half = 0; half < 2; half++) {
                int oc = (o0 & 511) + wm * 32 + ma * 16 + (lane >> 2) + half * 8;
                int p = oc >> 6, d = oc & 63;
#pragma unroll
                for (int na = 0; na < 8; na++) {
                    int n = nt * 128 + wn * 64 + na * 8 + (lane & 3) * 2;
                    unsigned short h0, l0, h1, l1;
                    split_bf(acc[ma][na][half * 2], h0, l0);
                    split_bf(acc[ma][na][half * 2 + 1], h1, l1);
                    size_t off = ((size_t)(b * P_ + p) * D_ + d) * N_ + n;
                    *(uint32_t*)&g_vh[off] = packus(h0, h1);
                    *(uint32_t*)&g_vl[off] = packus(l0, l1);
                }
            }
        }
    }
}

// ---------------- kernel 2: flash attention via mma.sync, Br=128, 256 threads ----------------
// 8 warps, warp wm owns q rows wm*16..+15; Bc=64 keys per tile.
// smem: Qh|Ql (18432 ea) + 2 x {Kh,Kl,Vh,Vl} (9216 ea) = 110592 B -> 2 CTAs/SM
#define ATT_SMEM (2 * 18432 + 2 * 4 * 9216)

__global__ __launch_bounds__(256, 2)
void attn_mma_kernel(float* __restrict__ out) {
    extern __shared__ char dynsm[];
    const int b  = blockIdx.z;
    const int p  = blockIdx.y;
    const int n0 = blockIdx.x * 128;
    const int tid = threadIdx.x;
    const int lane = tid & 31, wm = tid >> 5;   // wm 0..7

    const uint32_t base = smem_u32(dynsm);
    const size_t hb  = (size_t)(b * P_ + p) * N_ * D_;
    const size_t hbV = (size_t)(b * P_ + p) * D_ * N_;

    // Q tiles (once): 128 rows x 64 bf16, hi/lo
#pragma unroll
    for (int it = 0; it < 4; it++) {
        int idx = tid + it * 256;                // 0..1023
        int row = idx >> 3, c8 = idx & 7;
        size_t g = hb + (size_t)(n0 + row) * D_ + c8 * 8;
        *(uint4*)(dynsm + row * 144 + c8 * 16)         = *(const uint4*)&g_qh[g];
        *(uint4*)(dynsm + 18432 + row * 144 + c8 * 16) = *(const uint4*)&g_ql[g];
    }

    auto issueKV = [&](int kt) {
        uint32_t buf = base + 36864 + (uint32_t)(kt & 1) * 36864;
#pragma unroll
        for (int it = 0; it < 2; it++) {
            int idx = tid + it * 256;            // 0..511
            int row = idx >> 3, c8 = idx & 7;
            uint32_t so = (uint32_t)(row * 144 + c8 * 16);
            size_t gk = hb + (size_t)(kt * 64 + row) * D_ + c8 * 8;
            size_t gv = hbV + (size_t)row * N_ + kt * 64 + c8 * 8;
            cpa16(buf + 0 * 9216 + so, g_kh + gk);
            cpa16(buf + 1 * 9216 + so, g_kl + gk);
            cpa16(buf + 2 * 9216 + so, g_vh + gv);
            cpa16(buf + 3 * 9216 + so, g_vl + gv);
        }
    };

    float m_i[2] = {-INFINITY, -INFINITY};
    float l_i[2] = {0.f, 0.f};
    float o_acc[8][4];
#pragma unroll
    for (int f = 0; f < 8; f++)
#pragma unroll
        for (int q = 0; q < 4; q++) o_acc[f][q] = 0.f;

    issueKV(0); CP_COMMIT();

    for (int kt = 0; kt < 16; kt++) {
        if (kt < 15) { issueKV(kt + 1); CP_COMMIT(); CP_WAIT(1); }
        else         { CP_WAIT(0); }
        __syncthreads();
        const uint32_t buf = base + 36864 + (uint32_t)(kt & 1) * 36864;
        const uint32_t Kh = buf, Kl = buf + 9216, Vh = buf + 18432, Vl = buf + 27648;

        // S = Q K^T (3-term split)
        float sc[8][4];
#pragma unroll
        for (int f = 0; f < 8; f++)
#pragma unroll
            for (int q = 0; q < 4; q++) sc[f][q] = 0.f;

#pragma unroll
        for (int ks = 0; ks < 4; ks++) {
            uint32_t aoff = (uint32_t)((wm * 16 + (lane & 15)) * 144 +
                                       ks * 32 + (lane >> 4) * 16);
            uint32_t qh[4], ql[4];
            ldsm4(base + aoff, qh);
            ldsm4(base + 18432 + aoff, ql);
#pragma unroll
            for (int f = 0; f < 8; f++) {
                uint32_t boff = (uint32_t)((f * 8 + (lane & 7)) * 144 +
                                           ks * 32 + ((lane >> 3) & 1) * 16);
                uint32_t kh[2], kl[2];
                ldsm2(Kh + boff, kh);
                ldsm2(Kl + boff, kl);
                mma16816(sc[f], qh, kh);
                mma16816(sc[f], qh, kl);
                mma16816(sc[f], ql, kh);
            }
        }

        // online softmax: thread rows r0=lane>>2, r1=r0+8 (within warp's 16 rows)
        float rm0 = -INFINITY, rm1 = -INFINITY;
#pragma unroll
        for (int f = 0; f < 8; f++) {
            rm0 = fmaxf(rm0, fmaxf(sc[f][0], sc[f][1]));
            rm1 = fmaxf(rm1, fmaxf(sc[f][2], sc[f][3]));
        }
        rm0 = fmaxf(rm0, __shfl_xor_sync(0xffffffffu, rm0, 1));
        rm0 = fmaxf(rm0, __shfl_xor_sync(0xffffffffu, rm0, 2));
        rm1 = fmaxf(rm1, __shfl_xor_sync(0xffffffffu, rm1, 1));
        rm1 = fmaxf(rm1, __shfl_xor_sync(0xffffffffu, rm1, 2));
        float mn0 = fmaxf(m_i[0], rm0), mn1 = fmaxf(m_i[1], rm1);
        float corr0 = __expf(m_i[0] - mn0), corr1 = __expf(m_i[1] - mn1);
        float rs0 = 0.f, rs1 = 0.f;
#pragma unroll
        for (int f = 0; f < 8; f++) {
            sc[f][0] = __expf(sc[f][0] - mn0);
            sc[f][1] = __expf(sc[f][1] - mn0);
            sc[f][2] = __expf(sc[f][2] - mn1);
            sc[f][3] = __expf(sc[f][3] - mn1);
            rs0 += sc[f][0] + sc[f][1];
            rs1 += sc[f][2] + sc[f][3];
        }
        rs0 += __shfl_xor_sync(0xffffffffu, rs0, 1);
        rs0 += __shfl_xor_sync(0xffffffffu, rs0, 2);
        rs1 += __shfl_xor_sync(0xffffffffu, rs1, 1);
        rs1 += __shfl_xor_sync(0xffffffffu, rs1, 2);
        l_i[0] = l_i[0] * corr0 + rs0;
        l_i[1] = l_i[1] * corr1 + rs1;
        m_i[0] = mn0; m_i[1] = mn1;
#pragma unroll
        for (int f = 0; f < 8; f++) {
            o_acc[f][0] *= corr0; o_acc[f][1] *= corr0;
            o_acc[f][2] *= corr1; o_acc[f][3] *= corr1;
        }

        // O += P V (P split in registers; V split in smem, [d][key] layout)
#pragma unroll
        for (int kc = 0; kc < 4; kc++) {
            const int f0 = 2 * kc, f1 = 2 * kc + 1;
            uint32_t ah[4], al[4];
            unsigned short h[8], l[8];
            split_bf(sc[f0][0], h[0], l[0]); split_bf(sc[f0][1], h[1], l[1]);
            split_bf(sc[f0][2], h[2], l[2]); split_bf(sc[f0][3], h[3], l[3]);
            split_bf(sc[f1][0], h[4], l[4]); split_bf(sc[f1][1], h[5], l[5]);
            split_bf(sc[f1][2], h[6], l[6]); split_bf(sc[f1][3], h[7], l[7]);
            ah[0] = packus(h[0], h[1]); ah[1] = packus(h[2], h[3]);
            ah[2] = packus(h[4], h[5]); ah[3] = packus(h[6], h[7]);
            al[0] = packus(l[0], l[1]); al[1] = packus(l[2], l[3]);
            al[2] = packus(l[4], l[5]); al[3] = packus(l[6], l[7]);
#pragma unroll
            for (int df = 0; df < 8; df++) {
                uint32_t boff = (uint32_t)((df * 8 + (lane & 7)) * 144 +
                                           kc * 32 + ((lane >> 3) & 1) * 16);
                uint32_t vh[2], vl[2];
                ldsm2(Vh + boff, vh);
                ldsm2(Vl + boff, vl);
                mma16816(o_acc[df], ah, vh);
                mma16816(o_acc[df], ah, vl);
                mma16816(o_acc[df], al, vh);
            }
        }
        __syncthreads();
    }

    // epilogue: normalize, stage [d][q] in smem, coalesced store out[b, p*64+d, n]
    float inv0 = 1.f / l_i[0], inv1 = 1.f / l_i[1];
    float* Os = (float*)(dynsm + 36864);   // [64 d][132]
#pragma unroll
    for (int df = 0; df < 8; df++) {
        int d0 = df * 8 + 2 * (lane & 3);
        int q0 = wm * 16 + (lane >> 2);
        Os[(d0 + 0) * 132 + q0]     = o_acc[df][0] * inv0;
        Os[(d0 + 1) * 132 + q0]     = o_acc[df][1] * inv0;
        Os[(d0 + 0) * 132 + q0 + 8] = o_acc[df][2] * inv1;
        Os[(d0 + 1) * 132 + q0 + 8] = o_acc[df][3] * inv1;
    }
    __syncthreads();
#pragma unroll
    for (int it = 0; it < 8; it++) {
        int idx = tid + it * 256;          // 0..2047 float4s
        int d = idx >> 5, q4 = (idx & 31) * 4;
        float4 v = *(float4*)&Os[d * 132 + q4];
        *(float4*)&out[((size_t)(b * C_ + p * 64 + d)) * N_ + n0 + q4] = v;
    }
}

// ---------------- launch ----------------
extern "C" void kernel_launch(void* const* d_in, const int* in_sizes, int n_in,
                              void* d_out, int out_size) {
    const float* x     = (const float*)d_in[0];
    const float* qkv_w = (const float*)d_in[1];
    const float* h_pos = (const float*)d_in[2];
    const float* w_pos = (const float*)d_in[3];
    float* out = (float*)d_out;

    rp_kernel<<<(P_ * N_ * D_ + 255) / 256, 256>>>(h_pos, w_pos);

    dim3 gs(32, 16, B_);   // n-tiles, c-tiles, batch
    split_x_kernel<<<gs, 256>>>(x);
    split_w_kernel<<<(3 * C_ * C_ / 4 + 255) / 256, 256>>>(qkv_w);

    cudaFuncSetAttribute(qkv_mma_kernel,
                         cudaFuncAttributeMaxDynamicSharedMemorySize, QKV_SMEM);
    dim3 g1(12, 8, B_);    // o-blocks, n-tiles, batch
    qkv_mma_kernel<<<g1, 256, QKV_SMEM>>>();

    cudaFuncSetAttribute(attn_mma_kernel,
                         cudaFuncAttributeMaxDynamicSharedMemorySize, ATT_SMEM);
    dim3 g2(8, P_, B_);    // q-tiles (128), heads, batch
    attn_mma_kernel<<<g2, 256, ATT_SMEM>>>(out);
}

// round 13
// speedup vs baseline: 6.6318x; 1.0498x over previous
#include <cuda_runtime.h>
#include <cuda_bf16.h>
#include <math.h>
#include <cstdint>

#define B_ 32
#define C_ 512
#define P_ 8
#define D_ 64
#define N_ 1024   // 32*32

// ---------------- scratch (__device__ globals: alloc-free rule) ----------------
__device__ __nv_bfloat16 g_qh[(size_t)B_ * P_ * N_ * D_];  // [b,p,n,d]
__device__ __nv_bfloat16 g_ql[(size_t)B_ * P_ * N_ * D_];
__device__ __nv_bfloat16 g_kh[(size_t)B_ * P_ * N_ * D_];  // [b,p,n,d] (k+rp)
__device__ __nv_bfloat16 g_kl[(size_t)B_ * P_ * N_ * D_];
__device__ __nv_bfloat16 g_vh[(size_t)B_ * P_ * D_ * N_];  // [b,p,d,n]
__device__ __nv_bfloat16 g_vl[(size_t)B_ * P_ * D_ * N_];
__device__ float g_rp[(size_t)P_ * N_ * D_];               // [p,n,d]
__device__ __nv_bfloat16 g_xh[(size_t)B_ * N_ * C_];       // x^T hi [b,n,c]
__device__ __nv_bfloat16 g_xl[(size_t)B_ * N_ * C_];
__device__ __nv_bfloat16 g_wh[(size_t)3 * C_ * C_];        // w hi [o,c]
__device__ __nv_bfloat16 g_wl[(size_t)3 * C_ * C_];

// ---------------- warp-MMA helpers (baseline ISA: sm_80+) ----------------
__device__ __forceinline__ uint32_t smem_u32(const void* p) {
    uint32_t a;
    asm("{ .reg .u64 t; cvta.to.shared.u64 t, %1; cvt.u32.u64 %0, t; }" : "=r"(a) : "l"(p));
    return a;
}
__device__ __forceinline__ void ldsm4(uint32_t a, uint32_t r[4]) {
    asm volatile("ldmatrix.sync.aligned.m8n8.x4.shared.b16 {%0,%1,%2,%3}, [%4];"
        : "=r"(r[0]), "=r"(r[1]), "=r"(r[2]), "=r"(r[3]) : "r"(a));
}
__device__ __forceinline__ void mma16816(float c[4], const uint32_t a[4], const uint32_t b[2]) {
    asm volatile("mma.sync.aligned.m16n8k16.row.col.f32.bf16.bf16.f32 "
        "{%0,%1,%2,%3}, {%4,%5,%6,%7}, {%8,%9}, {%0,%1,%2,%3};"
        : "+f"(c[0]), "+f"(c[1]), "+f"(c[2]), "+f"(c[3])
        : "r"(a[0]), "r"(a[1]), "r"(a[2]), "r"(a[3]), "r"(b[0]), "r"(b[1]));
}
__device__ __forceinline__ void cpa16(uint32_t s, const void* g) {
    asm volatile("cp.async.cg.shared.global [%0], [%1], 16;" :: "r"(s), "l"(g));
}
#define CP_COMMIT()  asm volatile("cp.async.commit_group;" ::: "memory")
#define CP_WAIT(n)   asm volatile("cp.async.wait_group %0;" :: "n"(n) : "memory")

__device__ __forceinline__ void split_bf(float f, unsigned short& h, unsigned short& l) {
    __nv_bfloat16 hb = __float2bfloat16(f);
    h = __bfloat16_as_ushort(hb);
    l = __bfloat16_as_ushort(__float2bfloat16(f - __bfloat162float(hb)));
}
__device__ __forceinline__ uint32_t packus(unsigned short lo, unsigned short hi) {
    return (uint32_t)lo | ((uint32_t)hi << 16);
}

// ---------------- kernel 0: relative position table [p,n,d] ----------------
__global__ void rp_kernel(const float* __restrict__ h_pos,
                          const float* __restrict__ w_pos) {
    int idx = blockIdx.x * blockDim.x + threadIdx.x;
    if (idx >= P_ * N_ * D_) return;
    int dd = idx & 63;
    int n  = (idx >> 6) & (N_ - 1);
    int p  = idx >> 16;
    int c  = p * 64 + dd;
    g_rp[idx] = h_pos[(n >> 5) * C_ + c] + w_pos[(n & 31) * C_ + c];
}

// ---------------- kernel 0b: split+transpose X -> bf16 hi/lo [b,n,c] ----------------
__global__ __launch_bounds__(256)
void split_x_kernel(const float* __restrict__ x) {
    __shared__ float ts[32][33];
    const int b  = blockIdx.z;
    const int c0 = blockIdx.y * 32;
    const int n0 = blockIdx.x * 32;
    const int t = threadIdx.x;
    const int r = t >> 3, q4 = (t & 7) * 4;
    float4 v = *(const float4*)&x[((size_t)b * C_ + c0 + r) * N_ + n0 + q4];
    ts[r][q4] = v.x; ts[r][q4 + 1] = v.y; ts[r][q4 + 2] = v.z; ts[r][q4 + 3] = v.w;
    __syncthreads();
    ushort4 hi, lo;
    float f[4];
#pragma unroll
    for (int i = 0; i < 4; i++) f[i] = ts[q4 + i][r];
    split_bf(f[0], hi.x, lo.x); split_bf(f[1], hi.y, lo.y);
    split_bf(f[2], hi.z, lo.z); split_bf(f[3], hi.w, lo.w);
    size_t o = ((size_t)b * N_ + n0 + r) * C_ + c0 + q4;
    *(ushort4*)&g_xh[o] = hi;
    *(ushort4*)&g_xl[o] = lo;
}

// ---------------- kernel 0c: split W -> bf16 hi/lo [o,c] ----------------
__global__ void split_w_kernel(const float* __restrict__ w) {
    int f4 = blockIdx.x * blockDim.x + threadIdx.x;
    if (f4 >= 3 * C_ * C_ / 4) return;
    float4 v = ((const float4*)w)[f4];
    ushort4 hi, lo;
    split_bf(v.x, hi.x, lo.x); split_bf(v.y, hi.y, lo.y);
    split_bf(v.z, hi.z, lo.z); split_bf(v.w, hi.w, lo.w);
    ((ushort4*)g_wh)[f4] = hi;
    ((ushort4*)g_wl)[f4] = lo;
}

// ---------------- kernel 1: QKV GEMM via mma.sync bf16 split, BK=32, 1 sync/stage ----------------
#define TILE_B 10240u           // 128 rows * 80 B (32 bf16 + 16B pad)
#define BUF_B  (4u * TILE_B)    // Wh | Wl | Xh | Xl
#define QKV_SMEM (2 * 4 * 10240)

__global__ __launch_bounds__(256, 2)
void qkv_mma_kernel() {
    extern __shared__ char dynsm[];
    const int b  = blockIdx.z;
    const int nt = blockIdx.y;
    const int ob = blockIdx.x;
    const int o0 = ob * 128;
    const int tid = threadIdx.x;
    const int lane = tid & 31, wid = tid >> 5;
    const int wm = wid & 3, wn = wid >> 2;   // 4 (M) x 2 (N) warps

    const uint32_t sb = smem_u32(dynsm);
    const bool aIsX = (ob < 8);              // q/k: A = X

    const __nv_bfloat16* wh = g_wh + (size_t)o0 * C_;
    const __nv_bfloat16* wl = g_wl + (size_t)o0 * C_;
    const __nv_bfloat16* xh = g_xh + ((size_t)b * N_ + nt * 128) * C_;
    const __nv_bfloat16* xl = g_xl + ((size_t)b * N_ + nt * 128) * C_;

    auto issue = [&](int ch) {
        const int kc0 = ch * 32;
        const uint32_t buf = sb + (uint32_t)(ch & 1) * BUF_B;
#pragma unroll
        for (int j = 0; j < 2; j++) {
            int flat = tid + j * 256;          // 0..511
            int row = flat >> 2, c4 = flat & 3;
            uint32_t so = (uint32_t)(row * 80 + c4 * 16);
            size_t go = (size_t)row * C_ + kc0 + c4 * 8;
            cpa16(buf + 0 * TILE_B + so, wh + go);
            cpa16(buf + 1 * TILE_B + so, wl + go);
            cpa16(buf + 2 * TILE_B + so, xh + go);
            cpa16(buf + 3 * TILE_B + so, xl + go);
        }
    };

    float acc[2][8][4];
#pragma unroll
    for (int ma = 0; ma < 2; ma++)
#pragma unroll
        for (int na = 0; na < 8; na++)
#pragma unroll
            for (int q = 0; q < 4; q++) acc[ma][na][q] = 0.f;

    issue(0); CP_COMMIT();
    for (int ch = 0; ch < 16; ch++) {
        CP_WAIT(0);
        __syncthreads();
        if (ch < 15) { issue(ch + 1); CP_COMMIT(); }
        const uint32_t buf = sb + (uint32_t)(ch & 1) * BUF_B;
        const uint32_t Ah = buf + (aIsX ? 2 * TILE_B : 0);
        const uint32_t Al = Ah + TILE_B;
        const uint32_t Bh = buf + (aIsX ? 0 : 2 * TILE_B);
        const uint32_t Bl = Bh + TILE_B;
#pragma unroll
        for (int ks = 0; ks < 2; ks++) {
            uint32_t ah[2][4], al[2][4];
#pragma unroll
            for (int ma = 0; ma < 2; ma++) {
                uint32_t aoff = (uint32_t)((wm * 32 + ma * 16 + (lane & 15)) * 80 +
                                           ks * 32 + (lane >> 4) * 16);
                ldsm4(Ah + aoff, ah[ma]);
                ldsm4(Al + aoff, al[ma]);
            }
#pragma unroll
            for (int pr = 0; pr < 4; pr++) {
                uint32_t boff = (uint32_t)((wn * 64 + pr * 16 + ((lane >> 4) & 1) * 8 +
                                            (lane & 7)) * 80 +
                                           ks * 32 + ((lane >> 3) & 1) * 16);
                uint32_t bh[4], bl[4];
                ldsm4(Bh + boff, bh);
                ldsm4(Bl + boff, bl);
#pragma unroll
                for (int ma = 0; ma < 2; ma++) {
                    mma16816(acc[ma][2 * pr], ah[ma], bh);
                    mma16816(acc[ma][2 * pr], ah[ma], bl);
                    mma16816(acc[ma][2 * pr], al[ma], bh);
                    mma16816(acc[ma][2 * pr + 1], ah[ma], bh + 2);
                    mma16816(acc[ma][2 * pr + 1], ah[ma], bl + 2);
                    mma16816(acc[ma][2 * pr + 1], al[ma], bh + 2);
                }
            }
        }
    }

    // ---- epilogue: split to bf16 hi/lo ----
    const int which = o0 >> 9;                 // 0=q 1=k 2=v
    if (aIsX) {
        __nv_bfloat16* dh = which ? g_kh : g_qh;
        __nv_bfloat16* dl = which ? g_kl : g_ql;
#pragma unroll
        for (int ma = 0; ma < 2; ma++) {
#pragma unroll
            for (int half = 0; half < 2; half++) {
                int nrow = nt * 128 + wm * 32 + ma * 16 + (lane >> 2) + half * 8;
#pragma unroll
                for (int na = 0; na < 8; na++) {
                    int oc = (o0 & 511) + wn * 64 + na * 8 + (lane & 3) * 2;
                    int p = oc >> 6, d = oc & 63;
                    float c0 = acc[ma][na][half * 2], c1 = acc[ma][na][half * 2 + 1];
                    if (which == 1) {
                        float2 r = *(const float2*)&g_rp[((size_t)p * N_ + nrow) * D_ + d];
                        c0 += r.x; c1 += r.y;
                    }
                    unsigned short h0, l0, h1, l1;
                    split_bf(c0, h0, l0); split_bf(c1, h1, l1);
                    size_t off = ((size_t)(b * P_ + p) * N_ + nrow) * D_ + d;
                    *(uint32_t*)&dh[off] = packus(h0, h1);
                    *(uint32_t*)&dl[off] = packus(l0, l1);
                }
            }
        }
    } else {
#pragma unroll
        for (int ma = 0; ma < 2; ma++) {
#pragma unroll
            for (int half = 0; half < 2; half++) {
                int oc = (o0 & 511) + wm * 32 + ma * 16 + (lane >> 2) + half * 8;
                int p = oc >> 6, d = oc & 63;
#pragma unroll
                for (int na = 0; na < 8; na++) {
                    int n = nt * 128 + wn * 64 + na * 8 + (lane & 3) * 2;
                    unsigned short h0, l0, h1, l1;
                    split_bf(acc[ma][na][half * 2], h0, l0);
                    split_bf(acc[ma][na][half * 2 + 1], h1, l1);
                    size_t off = ((size_t)(b * P_ + p) * D_ + d) * N_ + n;
                    *(uint32_t*)&g_vh[off] = packus(h0, h1);
                    *(uint32_t*)&g_vl[off] = packus(l0, l1);
                }
            }
        }
    }
}

// ---------------- kernel 2: flash attention via mma.sync, Br=128, 1 sync/stage ----------------
#define ATT_SMEM (2 * 18432 + 2 * 4 * 9216)

__global__ __launch_bounds__(256, 2)
void attn_mma_kernel(float* __restrict__ out) {
    extern __shared__ char dynsm[];
    const int b  = blockIdx.z;
    const int p  = blockIdx.y;
    const int n0 = blockIdx.x * 128;
    const int tid = threadIdx.x;
    const int lane = tid & 31, wm = tid >> 5;   // wm 0..7

    const uint32_t base = smem_u32(dynsm);
    const size_t hb  = (size_t)(b * P_ + p) * N_ * D_;
    const size_t hbV = (size_t)(b * P_ + p) * D_ * N_;

    // Q tiles (once): 128 rows x 64 bf16, hi/lo
#pragma unroll
    for (int it = 0; it < 4; it++) {
        int idx = tid + it * 256;                // 0..1023
        int row = idx >> 3, c8 = idx & 7;
        size_t g = hb + (size_t)(n0 + row) * D_ + c8 * 8;
        *(uint4*)(dynsm + row * 144 + c8 * 16)         = *(const uint4*)&g_qh[g];
        *(uint4*)(dynsm + 18432 + row * 144 + c8 * 16) = *(const uint4*)&g_ql[g];
    }

    auto issueKV = [&](int kt) {
        uint32_t buf = base + 36864 + (uint32_t)(kt & 1) * 36864;
#pragma unroll
        for (int it = 0; it < 2; it++) {
            int idx = tid + it * 256;            // 0..511
            int row = idx >> 3, c8 = idx & 7;
            uint32_t so = (uint32_t)(row * 144 + c8 * 16);
            size_t gk = hb + (size_t)(kt * 64 + row) * D_ + c8 * 8;
            size_t gv = hbV + (size_t)row * N_ + kt * 64 + c8 * 8;
            cpa16(buf + 0 * 9216 + so, g_kh + gk);
            cpa16(buf + 1 * 9216 + so, g_kl + gk);
            cpa16(buf + 2 * 9216 + so, g_vh + gv);
            cpa16(buf + 3 * 9216 + so, g_vl + gv);
        }
    };

    float m_i[2] = {-INFINITY, -INFINITY};
    float l_i[2] = {0.f, 0.f};
    float o_acc[8][4];
#pragma unroll
    for (int f = 0; f < 8; f++)
#pragma unroll
        for (int q = 0; q < 4; q++) o_acc[f][q] = 0.f;

    issueKV(0); CP_COMMIT();

    for (int kt = 0; kt < 16; kt++) {
        CP_WAIT(0);
        __syncthreads();
        if (kt < 15) { issueKV(kt + 1); CP_COMMIT(); }
        const uint32_t buf = base + 36864 + (uint32_t)(kt & 1) * 36864;
        const uint32_t Kh = buf, Kl = buf + 9216, Vh = buf + 18432, Vl = buf + 27648;

        // S = Q K^T (3-term split)
        float sc[8][4];
#pragma unroll
        for (int f = 0; f < 8; f++)
#pragma unroll
            for (int q = 0; q < 4; q++) sc[f][q] = 0.f;

#pragma unroll
        for (int ks = 0; ks < 4; ks++) {
            uint32_t aoff = (uint32_t)((wm * 16 + (lane & 15)) * 144 +
                                       ks * 32 + (lane >> 4) * 16);
            uint32_t qh[4], ql[4];
            ldsm4(base + aoff, qh);
            ldsm4(base + 18432 + aoff, ql);
#pragma unroll
            for (int pr = 0; pr < 4; pr++) {
                uint32_t boff = (uint32_t)((pr * 16 + ((lane >> 4) & 1) * 8 +
                                            (lane & 7)) * 144 +
                                           ks * 32 + ((lane >> 3) & 1) * 16);
                uint32_t kh[4], kl[4];
                ldsm4(Kh + boff, kh);
                ldsm4(Kl + boff, kl);
                mma16816(sc[2 * pr], qh, kh);
                mma16816(sc[2 * pr], qh, kl);
                mma16816(sc[2 * pr], ql, kh);
                mma16816(sc[2 * pr + 1], qh, kh + 2);
                mma16816(sc[2 * pr + 1], qh, kl + 2);
                mma16816(sc[2 * pr + 1], ql, kh + 2);
            }
        }

        // online softmax: thread rows r0=lane>>2, r1=r0+8 (within warp's 16 rows)
        float rm0 = -INFINITY, rm1 = -INFINITY;
#pragma unroll
        for (int f = 0; f < 8; f++) {
            rm0 = fmaxf(rm0, fmaxf(sc[f][0], sc[f][1]));
            rm1 = fmaxf(rm1, fmaxf(sc[f][2], sc[f][3]));
        }
        rm0 = fmaxf(rm0, __shfl_xor_sync(0xffffffffu, rm0, 1));
        rm0 = fmaxf(rm0, __shfl_xor_sync(0xffffffffu, rm0, 2));
        rm1 = fmaxf(rm1, __shfl_xor_sync(0xffffffffu, rm1, 1));
        rm1 = fmaxf(rm1, __shfl_xor_sync(0xffffffffu, rm1, 2));
        float mn0 = fmaxf(m_i[0], rm0), mn1 = fmaxf(m_i[1], rm1);
        float corr0 = __expf(m_i[0] - mn0), corr1 = __expf(m_i[1] - mn1);
        float rs0 = 0.f, rs1 = 0.f;
#pragma unroll
        for (int f = 0; f < 8; f++) {
            sc[f][0] = __expf(sc[f][0] - mn0);
            sc[f][1] = __expf(sc[f][1] - mn0);
            sc[f][2] = __expf(sc[f][2] - mn1);
            sc[f][3] = __expf(sc[f][3] - mn1);
            rs0 += sc[f][0] + sc[f][1];
            rs1 += sc[f][2] + sc[f][3];
        }
        rs0 += __shfl_xor_sync(0xffffffffu, rs0, 1);
        rs0 += __shfl_xor_sync(0xffffffffu, rs0, 2);
        rs1 += __shfl_xor_sync(0xffffffffu, rs1, 1);
        rs1 += __shfl_xor_sync(0xffffffffu, rs1, 2);
        l_i[0] = l_i[0] * corr0 + rs0;
        l_i[1] = l_i[1] * corr1 + rs1;
        m_i[0] = mn0; m_i[1] = mn1;
#pragma unroll
        for (int f = 0; f < 8; f++) {
            o_acc[f][0] *= corr0; o_acc[f][1] *= corr0;
            o_acc[f][2] *= corr1; o_acc[f][3] *= corr1;
        }

        // O += P V (P split in registers; V split in smem, [d][key] layout)
#pragma unroll
        for (int kc = 0; kc < 4; kc++) {
            const int f0 = 2 * kc, f1 = 2 * kc + 1;
            uint32_t ah[4], al[4];
            unsigned short h[8], l[8];
            split_bf(sc[f0][0], h[0], l[0]); split_bf(sc[f0][1], h[1], l[1]);
            split_bf(sc[f0][2], h[2], l[2]); split_bf(sc[f0][3], h[3], l[3]);
            split_bf(sc[f1][0], h[4], l[4]); split_bf(sc[f1][1], h[5], l[5]);
            split_bf(sc[f1][2], h[6], l[6]); split_bf(sc[f1][3], h[7], l[7]);
            ah[0] = packus(h[0], h[1]); ah[1] = packus(h[2], h[3]);
            ah[2] = packus(h[4], h[5]); ah[3] = packus(h[6], h[7]);
            al[0] = packus(l[0], l[1]); al[1] = packus(l[2], l[3]);
            al[2] = packus(l[4], l[5]); al[3] = packus(l[6], l[7]);
#pragma unroll
            for (int pr = 0; pr < 4; pr++) {
                uint32_t boff = (uint32_t)((pr * 16 + ((lane >> 4) & 1) * 8 +
                                            (lane & 7)) * 144 +
                                           kc * 32 + ((lane >> 3) & 1) * 16);
                uint32_t vh[4], vl[4];
                ldsm4(Vh + boff, vh);
                ldsm4(Vl + boff, vl);
                mma16816(o_acc[2 * pr], ah, vh);
                mma16816(o_acc[2 * pr], ah, vl);
                mma16816(o_acc[2 * pr], al, vh);
                mma16816(o_acc[2 * pr + 1], ah, vh + 2);
                mma16816(o_acc[2 * pr + 1], ah, vl + 2);
                mma16816(o_acc[2 * pr + 1], al, vh + 2);
            }
        }
    }

    // epilogue: normalize, stage [d][q] in smem, coalesced store out[b, p*64+d, n]
    float inv0 = 1.f / l_i[0], inv1 = 1.f / l_i[1];
    float* Os = (float*)(dynsm + 36864);   // [64 d][132]
#pragma unroll
    for (int df = 0; df < 8; df++) {
        int d0 = df * 8 + 2 * (lane & 3);
        int q0 = wm * 16 + (lane >> 2);
        Os[(d0 + 0) * 132 + q0]     = o_acc[df][0] * inv0;
        Os[(d0 + 1) * 132 + q0]     = o_acc[df][1] * inv0;
        Os[(d0 + 0) * 132 + q0 + 8] = o_acc[df][2] * inv1;
        Os[(d0 + 1) * 132 + q0 + 8] = o_acc[df][3] * inv1;
    }
    __syncthreads();
#pragma unroll
    for (int it = 0; it < 8; it++) {
        int idx = tid + it * 256;          // 0..2047 float4s
        int d = idx >> 5, q4 = (idx & 31) * 4;
        float4 v = *(float4*)&Os[d * 132 + q4];
        *(float4*)&out[((size_t)(b * C_ + p * 64 + d)) * N_ + n0 + q4] = v;
    }
}

// ---------------- launch ----------------
extern "C" void kernel_launch(void* const* d_in, const int* in_sizes, int n_in,
                              void* d_out, int out_size) {
    const float* x     = (const float*)d_in[0];
    const float* qkv_w = (const float*)d_in[1];
    const float* h_pos = (const float*)d_in[2];
    const float* w_pos = (const float*)d_in[3];
    float* out = (float*)d_out;

    rp_kernel<<<(P_ * N_ * D_ + 255) / 256, 256>>>(h_pos, w_pos);

    dim3 gs(32, 16, B_);   // n-tiles, c-tiles, batch
    split_x_kernel<<<gs, 256>>>(x);
    split_w_kernel<<<(3 * C_ * C_ / 4 + 255) / 256, 256>>>(qkv_w);

    cudaFuncSetAttribute(qkv_mma_kernel,
                         cudaFuncAttributeMaxDynamicSharedMemorySize, QKV_SMEM);
    dim3 g1(12, 8, B_);    // o-blocks, n-tiles, batch
    qkv_mma_kernel<<<g1, 256, QKV_SMEM>>>();

    cudaFuncSetAttribute(attn_mma_kernel,
                         cudaFuncAttributeMaxDynamicSharedMemorySize, ATT_SMEM);
    dim3 g2(8, P_, B_);    // q-tiles (128), heads, batch
    attn_mma_kernel<<<g2, 256, ATT_SMEM>>>(out);
}

// round 14
// speedup vs baseline: 7.3146x; 1.1030x over previous
#include <cuda_runtime.h>
#include <cuda_fp16.h>
#include <math.h>
#include <cstdint>

#define B_ 32
#define C_ 512
#define P_ 8
#define D_ 64
#define N_ 1024   // 32*32

// ---------------- scratch (__device__ globals: alloc-free rule) ----------------
__device__ __half g_qh[(size_t)B_ * P_ * N_ * D_];  // [b,p,n,d]
__device__ __half g_ql[(size_t)B_ * P_ * N_ * D_];
__device__ __half g_kh[(size_t)B_ * P_ * N_ * D_];  // [b,p,n,d] (k+rp)
__device__ __half g_kl[(size_t)B_ * P_ * N_ * D_];
__device__ __half g_vh[(size_t)B_ * P_ * D_ * N_];  // [b,p,d,n]
__device__ __half g_vl[(size_t)B_ * P_ * D_ * N_];
__device__ float g_rp[(size_t)P_ * N_ * D_];        // [p,n,d]
__device__ __half g_xh[(size_t)B_ * N_ * C_];       // x^T hi [b,n,c]
__device__ __half g_xl[(size_t)B_ * N_ * C_];
__device__ __half g_wh[(size_t)3 * C_ * C_];        // w hi [o,c]
__device__ __half g_wl[(size_t)3 * C_ * C_];

// ---------------- warp-MMA helpers (baseline ISA: sm_80+) ----------------
__device__ __forceinline__ uint32_t smem_u32(const void* p) {
    uint32_t a;
    asm("{ .reg .u64 t; cvta.to.shared.u64 t, %1; cvt.u32.u64 %0, t; }" : "=r"(a) : "l"(p));
    return a;
}
__device__ __forceinline__ void ldsm4(uint32_t a, uint32_t r[4]) {
    asm volatile("ldmatrix.sync.aligned.m8n8.x4.shared.b16 {%0,%1,%2,%3}, [%4];"
        : "=r"(r[0]), "=r"(r[1]), "=r"(r[2]), "=r"(r[3]) : "r"(a));
}
__device__ __forceinline__ void mma16816(float c[4], const uint32_t a[4], const uint32_t b[2]) {
    asm volatile("mma.sync.aligned.m16n8k16.row.col.f32.f16.f16.f32 "
        "{%0,%1,%2,%3}, {%4,%5,%6,%7}, {%8,%9}, {%0,%1,%2,%3};"
        : "+f"(c[0]), "+f"(c[1]), "+f"(c[2]), "+f"(c[3])
        : "r"(a[0]), "r"(a[1]), "r"(a[2]), "r"(a[3]), "r"(b[0]), "r"(b[1]));
}
__device__ __forceinline__ void cpa16(uint32_t s, const void* g) {
    asm volatile("cp.async.cg.shared.global [%0], [%1], 16;" :: "r"(s), "l"(g));
}
#define CP_COMMIT()  asm volatile("cp.async.commit_group;" ::: "memory")
#define CP_WAIT(n)   asm volatile("cp.async.wait_group %0;" :: "n"(n) : "memory")

__device__ __forceinline__ void split_h(float f, unsigned short& h, unsigned short& l) {
    __half hb = __float2half_rn(f);
    h = __half_as_ushort(hb);
    l = __half_as_ushort(__float2half_rn(f - __half2float(hb)));
}
__device__ __forceinline__ unsigned short h16(float f) {
    return __half_as_ushort(__float2half_rn(f));
}
__device__ __forceinline__ uint32_t packus(unsigned short lo, unsigned short hi) {
    return (uint32_t)lo | ((uint32_t)hi << 16);
}

// ---------------- kernel 0: relative position table [p,n,d] ----------------
__global__ void rp_kernel(const float* __restrict__ h_pos,
                          const float* __restrict__ w_pos) {
    int idx = blockIdx.x * blockDim.x + threadIdx.x;
    if (idx >= P_ * N_ * D_) return;
    int dd = idx & 63;
    int n  = (idx >> 6) & (N_ - 1);
    int p  = idx >> 16;
    int c  = p * 64 + dd;
    g_rp[idx] = h_pos[(n >> 5) * C_ + c] + w_pos[(n & 31) * C_ + c];
}

// ---------------- kernel 0b: split+transpose X -> fp16 hi/lo [b,n,c] ----------------
__global__ __launch_bounds__(256)
void split_x_kernel(const float* __restrict__ x) {
    __shared__ float ts[32][33];
    const int b  = blockIdx.z;
    const int c0 = blockIdx.y * 32;
    const int n0 = blockIdx.x * 32;
    const int t = threadIdx.x;
    const int r = t >> 3, q4 = (t & 7) * 4;
    float4 v = *(const float4*)&x[((size_t)b * C_ + c0 + r) * N_ + n0 + q4];
    ts[r][q4] = v.x; ts[r][q4 + 1] = v.y; ts[r][q4 + 2] = v.z; ts[r][q4 + 3] = v.w;
    __syncthreads();
    ushort4 hi, lo;
    float f[4];
#pragma unroll
    for (int i = 0; i < 4; i++) f[i] = ts[q4 + i][r];
    split_h(f[0], hi.x, lo.x); split_h(f[1], hi.y, lo.y);
    split_h(f[2], hi.z, lo.z); split_h(f[3], hi.w, lo.w);
    size_t o = ((size_t)b * N_ + n0 + r) * C_ + c0 + q4;
    *(ushort4*)&g_xh[o] = hi;
    *(ushort4*)&g_xl[o] = lo;
}

// ---------------- kernel 0c: split W -> fp16 hi/lo [o,c] ----------------
__global__ void split_w_kernel(const float* __restrict__ w) {
    int f4 = blockIdx.x * blockDim.x + threadIdx.x;
    if (f4 >= 3 * C_ * C_ / 4) return;
    float4 v = ((const float4*)w)[f4];
    ushort4 hi, lo;
    split_h(v.x, hi.x, lo.x); split_h(v.y, hi.y, lo.y);
    split_h(v.z, hi.z, lo.z); split_h(v.w, hi.w, lo.w);
    ((ushort4*)g_wh)[f4] = hi;
    ((ushort4*)g_wl)[f4] = lo;
}

// ---------------- kernel 1: QKV GEMM via mma.sync fp16 split ----------------
// q/k blocks (ob 0..7): A=X, B=W, 3-term -> [b,p,n,d] fp16 hi/lo (+rp for k)
// v  blocks (ob 8..11): A=W, B=X, 2-term (Wh only) -> [b,p,d,n] fp16 hi/lo
#define TILE_B 10240u           // 128 rows * 80 B (32 fp16 + 16B pad)
#define BUF_B  (4u * TILE_B)    // Wh | Wl | Xh | Xl
#define QKV_SMEM (2 * 4 * 10240)

__global__ __launch_bounds__(256, 2)
void qkv_mma_kernel() {
    extern __shared__ char dynsm[];
    const int b  = blockIdx.z;
    const int nt = blockIdx.y;
    const int ob = blockIdx.x;
    const int o0 = ob * 128;
    const int tid = threadIdx.x;
    const int lane = tid & 31, wid = tid >> 5;
    const int wm = wid & 3, wn = wid >> 2;   // 4 (M) x 2 (N) warps

    const uint32_t sb = smem_u32(dynsm);
    const bool aIsX = (ob < 8);              // q/k: A = X

    const __half* wh = g_wh + (size_t)o0 * C_;
    const __half* wl = g_wl + (size_t)o0 * C_;
    const __half* xh = g_xh + ((size_t)b * N_ + nt * 128) * C_;
    const __half* xl = g_xl + ((size_t)b * N_ + nt * 128) * C_;

    auto issue = [&](int ch) {
        const int kc0 = ch * 32;
        const uint32_t buf = sb + (uint32_t)(ch & 1) * BUF_B;
#pragma unroll
        for (int j = 0; j < 2; j++) {
            int flat = tid + j * 256;          // 0..511
            int row = flat >> 2, c4 = flat & 3;
            uint32_t so = (uint32_t)(row * 80 + c4 * 16);
            size_t go = (size_t)row * C_ + kc0 + c4 * 8;
            cpa16(buf + 0 * TILE_B + so, wh + go);
            cpa16(buf + 1 * TILE_B + so, wl + go);
            cpa16(buf + 2 * TILE_B + so, xh + go);
            cpa16(buf + 3 * TILE_B + so, xl + go);
        }
    };

    float acc[2][8][4];
#pragma unroll
    for (int ma = 0; ma < 2; ma++)
#pragma unroll
        for (int na = 0; na < 8; na++)
#pragma unroll
            for (int q = 0; q < 4; q++) acc[ma][na][q] = 0.f;

    issue(0); CP_COMMIT();
    for (int ch = 0; ch < 16; ch++) {
        CP_WAIT(0);
        __syncthreads();
        if (ch < 15) { issue(ch + 1); CP_COMMIT(); }
        const uint32_t buf = sb + (uint32_t)(ch & 1) * BUF_B;
        const uint32_t Ah = buf + (aIsX ? 2 * TILE_B : 0);
        const uint32_t Al = Ah + TILE_B;
        const uint32_t Bh = buf + (aIsX ? 0 : 2 * TILE_B);
        const uint32_t Bl = Bh + TILE_B;
#pragma unroll
        for (int ks = 0; ks < 2; ks++) {
            uint32_t ah[2][4], al[2][4];
#pragma unroll
            for (int ma = 0; ma < 2; ma++) {
                uint32_t aoff = (uint32_t)((wm * 32 + ma * 16 + (lane & 15)) * 80 +
                                           ks * 32 + (lane >> 4) * 16);
                ldsm4(Ah + aoff, ah[ma]);
                if (aIsX) ldsm4(Al + aoff, al[ma]);
            }
#pragma unroll
            for (int pr = 0; pr < 4; pr++) {
                uint32_t boff = (uint32_t)((wn * 64 + pr * 16 + ((lane >> 4) & 1) * 8 +
                                            (lane & 7)) * 80 +
                                           ks * 32 + ((lane >> 3) & 1) * 16);
                uint32_t bh[4], bl[4];
                ldsm4(Bh + boff, bh);
                ldsm4(Bl + boff, bl);
                if (aIsX) {
                    // term-major sweep: hh x4, hl x4, lh x4 (RAW distance 4)
                    mma16816(acc[0][2 * pr],     ah[0], bh);
                    mma16816(acc[1][2 * pr],     ah[1], bh);
                    mma16816(acc[0][2 * pr + 1], ah[0], bh + 2);
                    mma16816(acc[1][2 * pr + 1], ah[1], bh + 2);
                    mma16816(acc[0][2 * pr],     ah[0], bl);
                    mma16816(acc[1][2 * pr],     ah[1], bl);
                    mma16816(acc[0][2 * pr + 1], ah[0], bl + 2);
                    mma16816(acc[1][2 * pr + 1], ah[1], bl + 2);
                    mma16816(acc[0][2 * pr],     al[0], bh);
                    mma16816(acc[1][2 * pr],     al[1], bh);
                    mma16816(acc[0][2 * pr + 1], al[0], bh + 2);
                    mma16816(acc[1][2 * pr + 1], al[1], bh + 2);
                } else {
                    // v path: 2-term (Wh·Xh + Wh·Xl = Wh·X, err ~2^-12)
                    mma16816(acc[0][2 * pr],     ah[0], bh);
                    mma16816(acc[1][2 * pr],     ah[1], bh);
                    mma16816(acc[0][2 * pr + 1], ah[0], bh + 2);
                    mma16816(acc[1][2 * pr + 1], ah[1], bh + 2);
                    mma16816(acc[0][2 * pr],     ah[0], bl);
                    mma16816(acc[1][2 * pr],     ah[1], bl);
                    mma16816(acc[0][2 * pr + 1], ah[0], bl + 2);
                    mma16816(acc[1][2 * pr + 1], ah[1], bl + 2);
                }
            }
        }
    }

    // ---- epilogue: split to fp16 hi/lo ----
    const int which = o0 >> 9;                 // 0=q 1=k 2=v
    if (aIsX) {
        __half* dh = which ? g_kh : g_qh;
        __half* dl = which ? g_kl : g_ql;
#pragma unroll
        for (int ma = 0; ma < 2; ma++) {
#pragma unroll
            for (int half = 0; half < 2; half++) {
                int nrow = nt * 128 + wm * 32 + ma * 16 + (lane >> 2) + half * 8;
#pragma unroll
                for (int na = 0; na < 8; na++) {
                    int oc = (o0 & 511) + wn * 64 + na * 8 + (lane & 3) * 2;
                    int p = oc >> 6, d = oc & 63;
                    float c0 = acc[ma][na][half * 2], c1 = acc[ma][na][half * 2 + 1];
                    if (which == 1) {
                        float2 r = *(const float2*)&g_rp[((size_t)p * N_ + nrow) * D_ + d];
                        c0 += r.x; c1 += r.y;
                    }
                    unsigned short h0, l0, h1, l1;
                    split_h(c0, h0, l0); split_h(c1, h1, l1);
                    size_t off = ((size_t)(b * P_ + p) * N_ + nrow) * D_ + d;
                    *(uint32_t*)&dh[off] = packus(h0, h1);
                    *(uint32_t*)&dl[off] = packus(l0, l1);
                }
            }
        }
    } else {
#pragma unroll
        for (int ma = 0; ma < 2; ma++) {
#pragma unroll
            for (int half = 0; half < 2; half++) {
                int oc = (o0 & 511) + wm * 32 + ma * 16 + (lane >> 2) + half * 8;
                int p = oc >> 6, d = oc & 63;
#pragma unroll
                for (int na = 0; na < 8; na++) {
                    int n = nt * 128 + wn * 64 + na * 8 + (lane & 3) * 2;
                    unsigned short h0, l0, h1, l1;
                    split_h(acc[ma][na][half * 2], h0, l0);
                    split_h(acc[ma][na][half * 2 + 1], h1, l1);
                    size_t off = ((size_t)(b * P_ + p) * D_ + d) * N_ + n;
                    *(uint32_t*)&g_vh[off] = packus(h0, h1);
                    *(uint32_t*)&g_vl[off] = packus(l0, l1);
                }
            }
        }
    }
}

// ---------------- kernel 2: flash attention via mma.sync fp16, Br=128 ----------------
// S: 3-term (Q,K fp16-pairs, err ~2^-22). PV: P single fp16 vs V 2-term.
#define ATT_SMEM (2 * 18432 + 2 * 4 * 9216)

__global__ __launch_bounds__(256, 2)
void attn_mma_kernel(float* __restrict__ out) {
    extern __shared__ char dynsm[];
    const int b  = blockIdx.z;
    const int p  = blockIdx.y;
    const int n0 = blockIdx.x * 128;
    const int tid = threadIdx.x;
    const int lane = tid & 31, wm = tid >> 5;   // wm 0..7

    const uint32_t base = smem_u32(dynsm);
    const size_t hb  = (size_t)(b * P_ + p) * N_ * D_;
    const size_t hbV = (size_t)(b * P_ + p) * D_ * N_;

    // Q tiles (once): 128 rows x 64 fp16, hi/lo
#pragma unroll
    for (int it = 0; it < 4; it++) {
        int idx = tid + it * 256;                // 0..1023
        int row = idx >> 3, c8 = idx & 7;
        size_t g = hb + (size_t)(n0 + row) * D_ + c8 * 8;
        *(uint4*)(dynsm + row * 144 + c8 * 16)         = *(const uint4*)&g_qh[g];
        *(uint4*)(dynsm + 18432 + row * 144 + c8 * 16) = *(const uint4*)&g_ql[g];
    }

    auto issueKV = [&](int kt) {
        uint32_t buf = base + 36864 + (uint32_t)(kt & 1) * 36864;
#pragma unroll
        for (int it = 0; it < 2; it++) {
            int idx = tid + it * 256;            // 0..511
            int row = idx >> 3, c8 = idx & 7;
            uint32_t so = (uint32_t)(row * 144 + c8 * 16);
            size_t gk = hb + (size_t)(kt * 64 + row) * D_ + c8 * 8;
            size_t gv = hbV + (size_t)row * N_ + kt * 64 + c8 * 8;
            cpa16(buf + 0 * 9216 + so, g_kh + gk);
            cpa16(buf + 1 * 9216 + so, g_kl + gk);
            cpa16(buf + 2 * 9216 + so, g_vh + gv);
            cpa16(buf + 3 * 9216 + so, g_vl + gv);
        }
    };

    float m_i[2] = {-INFINITY, -INFINITY};
    float l_i[2] = {0.f, 0.f};
    float o_acc[8][4];
#pragma unroll
    for (int f = 0; f < 8; f++)
#pragma unroll
        for (int q = 0; q < 4; q++) o_acc[f][q] = 0.f;

    issueKV(0); CP_COMMIT();

    for (int kt = 0; kt < 16; kt++) {
        CP_WAIT(0);
        __syncthreads();
        if (kt < 15) { issueKV(kt + 1); CP_COMMIT(); }
        const uint32_t buf = base + 36864 + (uint32_t)(kt & 1) * 36864;
        const uint32_t Kh = buf, Kl = buf + 9216, Vh = buf + 18432, Vl = buf + 27648;

        // S = Q K^T (3-term split)
        float sc[8][4];
#pragma unroll
        for (int f = 0; f < 8; f++)
#pragma unroll
            for (int q = 0; q < 4; q++) sc[f][q] = 0.f;

#pragma unroll
        for (int ks = 0; ks < 4; ks++) {
            uint32_t aoff = (uint32_t)((wm * 16 + (lane & 15)) * 144 +
                                       ks * 32 + (lane >> 4) * 16);
            uint32_t qh[4], ql[4];
            ldsm4(base + aoff, qh);
            ldsm4(base + 18432 + aoff, ql);
#pragma unroll
            for (int pr = 0; pr < 4; pr++) {
                uint32_t boff = (uint32_t)((pr * 16 + ((lane >> 4) & 1) * 8 +
                                            (lane & 7)) * 144 +
                                           ks * 32 + ((lane >> 3) & 1) * 16);
                uint32_t kh[4], kl[4];
                ldsm4(Kh + boff, kh);
                ldsm4(Kl + boff, kl);
                mma16816(sc[2 * pr],     qh, kh);
                mma16816(sc[2 * pr + 1], qh, kh + 2);
                mma16816(sc[2 * pr],     qh, kl);
                mma16816(sc[2 * pr + 1], qh, kl + 2);
                mma16816(sc[2 * pr],     ql, kh);
                mma16816(sc[2 * pr + 1], ql, kh + 2);
            }
        }

        // online softmax: thread rows r0=lane>>2, r1=r0+8 (within warp's 16 rows)
        float rm0 = -INFINITY, rm1 = -INFINITY;
#pragma unroll
        for (int f = 0; f < 8; f++) {
            rm0 = fmaxf(rm0, fmaxf(sc[f][0], sc[f][1]));
            rm1 = fmaxf(rm1, fmaxf(sc[f][2], sc[f][3]));
        }
        rm0 = fmaxf(rm0, __shfl_xor_sync(0xffffffffu, rm0, 1));
        rm0 = fmaxf(rm0, __shfl_xor_sync(0xffffffffu, rm0, 2));
        rm1 = fmaxf(rm1, __shfl_xor_sync(0xffffffffu, rm1, 1));
        rm1 = fmaxf(rm1, __shfl_xor_sync(0xffffffffu, rm1, 2));
        float mn0 = fmaxf(m_i[0], rm0), mn1 = fmaxf(m_i[1], rm1);
        float corr0 = __expf(m_i[0] - mn0), corr1 = __expf(m_i[1] - mn1);
        float rs0 = 0.f, rs1 = 0.f;
#pragma unroll
        for (int f = 0; f < 8; f++) {
            sc[f][0] = __expf(sc[f][0] - mn0);
            sc[f][1] = __expf(sc[f][1] - mn0);
            sc[f][2] = __expf(sc[f][2] - mn1);
            sc[f][3] = __expf(sc[f][3] - mn1);
            rs0 += sc[f][0] + sc[f][1];
            rs1 += sc[f][2] + sc[f][3];
        }
        rs0 += __shfl_xor_sync(0xffffffffu, rs0, 1);
        rs0 += __shfl_xor_sync(0xffffffffu, rs0, 2);
        rs1 += __shfl_xor_sync(0xffffffffu, rs1, 1);
        rs1 += __shfl_xor_sync(0xffffffffu, rs1, 2);
        l_i[0] = l_i[0] * corr0 + rs0;
        l_i[1] = l_i[1] * corr1 + rs1;
        m_i[0] = mn0; m_i[1] = mn1;
#pragma unroll
        for (int f = 0; f < 8; f++) {
            o_acc[f][0] *= corr0; o_acc[f][1] *= corr0;
            o_acc[f][2] *= corr1; o_acc[f][3] *= corr1;
        }

        // O += P V : P single fp16 in registers, V 2-term in smem ([d][key])
#pragma unroll
        for (int kc = 0; kc < 4; kc++) {
            const int f0 = 2 * kc, f1 = 2 * kc + 1;
            uint32_t ah[4];
            ah[0] = packus(h16(sc[f0][0]), h16(sc[f0][1]));
            ah[1] = packus(h16(sc[f0][2]), h16(sc[f0][3]));
            ah[2] = packus(h16(sc[f1][0]), h16(sc[f1][1]));
            ah[3] = packus(h16(sc[f1][2]), h16(sc[f1][3]));
#pragma unroll
            for (int pr = 0; pr < 4; pr++) {
                uint32_t boff = (uint32_t)((pr * 16 + ((lane >> 4) & 1) * 8 +
                                            (lane & 7)) * 144 +
                                           kc * 32 + ((lane >> 3) & 1) * 16);
                uint32_t vh[4], vl[4];
                ldsm4(Vh + boff, vh);
                ldsm4(Vl + boff, vl);
                mma16816(o_acc[2 * pr],     ah, vh);
                mma16816(o_acc[2 * pr + 1], ah, vh + 2);
                mma16816(o_acc[2 * pr],     ah, vl);
                mma16816(o_acc[2 * pr + 1], ah, vl + 2);
            }
        }
    }

    // epilogue: normalize, stage [d][q] in smem, coalesced store out[b, p*64+d, n]
    float inv0 = 1.f / l_i[0], inv1 = 1.f / l_i[1];
    float* Os = (float*)(dynsm + 36864);   // [64 d][132]
#pragma unroll
    for (int df = 0; df < 8; df++) {
        int d0 = df * 8 + 2 * (lane & 3);
        int q0 = wm * 16 + (lane >> 2);
        Os[(d0 + 0) * 132 + q0]     = o_acc[df][0] * inv0;
        Os[(d0 + 1) * 132 + q0]     = o_acc[df][1] * inv0;
        Os[(d0 + 0) * 132 + q0 + 8] = o_acc[df][2] * inv1;
        Os[(d0 + 1) * 132 + q0 + 8] = o_acc[df][3] * inv1;
    }
    __syncthreads();
#pragma unroll
    for (int it = 0; it < 8; it++) {
        int idx = tid + it * 256;          // 0..2047 float4s
        int d = idx >> 5, q4 = (idx & 31) * 4;
        float4 v = *(float4*)&Os[d * 132 + q4];
        *(float4*)&out[((size_t)(b * C_ + p * 64 + d)) * N_ + n0 + q4] = v;
    }
}

// ---------------- launch ----------------
extern "C" void kernel_launch(void* const* d_in, const int* in_sizes, int n_in,
                              void* d_out, int out_size) {
    const float* x     = (const float*)d_in[0];
    const float* qkv_w = (const float*)d_in[1];
    const float* h_pos = (const float*)d_in[2];
    const float* w_pos = (const float*)d_in[3];
    float* out = (float*)d_out;

    rp_kernel<<<(P_ * N_ * D_ + 255) / 256, 256>>>(h_pos, w_pos);

    dim3 gs(32, 16, B_);   // n-tiles, c-tiles, batch
    split_x_kernel<<<gs, 256>>>(x);
    split_w_kernel<<<(3 * C_ * C_ / 4 + 255) / 256, 256>>>(qkv_w);

    cudaFuncSetAttribute(qkv_mma_kernel,
                         cudaFuncAttributeMaxDynamicSharedMemorySize, QKV_SMEM);
    dim3 g1(12, 8, B_);    // o-blocks, n-tiles, batch
    qkv_mma_kernel<<<g1, 256, QKV_SMEM>>>();

    cudaFuncSetAttribute(attn_mma_kernel,
                         cudaFuncAttributeMaxDynamicSharedMemorySize, ATT_SMEM);
    dim3 g2(8, P_, B_);    // q-tiles (128), heads, batch
    attn_mma_kernel<<<g2, 256, ATT_SMEM>>>(out);
}